// round 6
// baseline (speedup 1.0000x reference)
#include <cuda_runtime.h>
#include <cuda_bf16.h>
#include <cstdint>

// ============================================================================
// CommNet via mma.sync m16n8k16 bf16 (compute_100-safe), 2 batches per CTA.
// M=128 rows/CTA, 512 threads = 16 warps; warp w owns n in [16w, 16w+16).
// h stored in SMEM as interleaved uint2{hi,lo} bf16x2 split pairs, layout
// sP[kpair][m].  D = Ahi*Bhi + Alo*Bhi + Ahi*Blo  (fp32 accumulators).
// G0 = h0 @ W1c computed once (step 0), parked in gmem, re-added steps 1-3.
// ============================================================================

#define HID    256
#define MROWS  128
#define STEPS  4
#define INVF   (1.0f/63.0f)
#define SP2    136             // uint2 pitch of sP[pair][*] (conflict-free)

// SMEM byte offsets
#define SP_OFF   0             // 128*136*8 = 139264
#define SV_OFF   139264        // float[2][256]
#define TV_OFF   141312        // float[2][256]
#define WD_OFF   143360        // float[256*16]
#define BD_OFF   159744        // float[16]
#define SMEM_BYTES 159808

// ---------------- device scratch ----------------
// gPk[g][(s*32+u)*32+lane] = {bh0,bh1,bl0,bl1}; g: 0=W1eff 1=W1c 2=W2
__device__ uint4 gPk[3][16384];
__device__ float gW1bT[HID * HID];          // W1b^T: [c][k]
__device__ float gG0[512 * 64 * 512];       // [cta][slot64][tid]  (64 MB)

// ---------------- fast bf16 split helpers ----------------
__device__ __forceinline__ uint32_t bf16x2_of(float lo_f, float hi_f) {
    // returns {high half: cvt(hi_f), low half: cvt(lo_f)}
    uint32_t r;
    asm("cvt.rn.bf16x2.f32 %0, %1, %2;" : "=r"(r) : "f"(hi_f), "f"(lo_f));
    return r;
}
__device__ __forceinline__ uint2 split2(float x0, float x1) {
    uint32_t hi = bf16x2_of(x0, x1);                       // low=x0, high=x1
    float h0 = __uint_as_float(hi << 16);
    float h1 = __uint_as_float(hi & 0xFFFF0000u);
    uint32_t lo = bf16x2_of(x0 - h0, x1 - h1);
    return make_uint2(hi, lo);
}
__device__ __forceinline__ float2 unsplit(uint2 p) {
    float f0 = __uint_as_float(p.x << 16)         + __uint_as_float(p.y << 16);
    float f1 = __uint_as_float(p.x & 0xFFFF0000u) + __uint_as_float(p.y & 0xFFFF0000u);
    return make_float2(f0, f1);
}

#define MMA(c, a, B0, B1)                                                      \
    asm volatile("mma.sync.aligned.m16n8k16.row.col.f32.bf16.bf16.f32 "        \
                 "{%0,%1,%2,%3},{%4,%5,%6,%7},{%8,%9},{%0,%1,%2,%3};"          \
                 : "+f"((c)[0]), "+f"((c)[1]), "+f"((c)[2]), "+f"((c)[3])      \
                 : "r"((a)[0]), "r"((a)[1]), "r"((a)[2]), "r"((a)[3]),         \
                   "r"(B0), "r"(B1));

// ---------------- prep kernels (identical pack layout to round 5) ----------
__global__ void prep_pack(const float* __restrict__ W1, const float* __restrict__ W2) {
    int idx = blockIdx.x * 256 + threadIdx.x;          // 3 * 16384
    int gm = idx >> 14;
    int r  = idx & 16383;
    int s  = r >> 10;
    int u  = (r >> 5) & 31;
    int l  = r & 31;
    int g  = l >> 2, t = l & 3;
    int n  = u * 8 + g;
    int kb = s * 16 + 2 * t;
    int ks[4] = { kb, kb + 1, kb + 8, kb + 9 };
    float v[4];
    #pragma unroll
    for (int q = 0; q < 4; ++q) {
        int k = ks[q];
        if (gm == 0)      v[q] = W1[k * HID + n] - INVF * W1[(HID + k) * HID + n];
        else if (gm == 1) v[q] = W1[(2 * HID + k) * HID + n];
        else              v[q] = W2[k * HID + n];
    }
    uint2 p0 = split2(v[0], v[1]);
    uint2 p1 = split2(v[2], v[3]);
    gPk[gm][r] = make_uint4(p0.x, p1.x, p0.y, p1.y);
}
__global__ void prep_t(const float* __restrict__ W1) {
    int c = blockIdx.x, k = threadIdx.x;
    gW1bT[c * HID + k] = W1[(HID + k) * HID + c];
}

// ---------------- GEMM pass: acc += splits(h) @ splits(B) -------------------
__device__ __forceinline__ void gemm_pass(const uint4* __restrict__ bp,
                                          float (&acc)[8][2][4],
                                          const uint2* __restrict__ sP,
                                          int w, int lane, int g, int t) {
    const uint4* bq = bp + w * 64 + lane;
    uint4 b0 = __ldg(bq);               // (s=0, j=0)
    uint4 b1 = __ldg(bq + 32);          // (s=0, j=1)
    #pragma unroll 2
    for (int s = 0; s < 16; ++s) {
        int sn = (s < 15) ? s + 1 : 15;
        uint4 nb0 = __ldg(bq + sn * 1024);
        uint4 nb1 = __ldg(bq + sn * 1024 + 32);
        const int kp0 = (s * 8 + t) * SP2;
        const int kp2 = kp0 + 4 * SP2;
        #pragma unroll
        for (int qd = 0; qd < 4; ++qd) {
            uint32_t ah[2][4], al[2][4];
            #pragma unroll
            for (int u = 0; u < 2; ++u) {
                int m0 = (qd * 2 + u) * 16 + g;
                uint2 pa = sP[kp0 + m0], pb = sP[kp0 + m0 + 8];
                uint2 pc = sP[kp2 + m0], pd = sP[kp2 + m0 + 8];
                ah[u][0] = pa.x; ah[u][1] = pb.x; ah[u][2] = pc.x; ah[u][3] = pd.x;
                al[u][0] = pa.y; al[u][1] = pb.y; al[u][2] = pc.y; al[u][3] = pd.y;
            }
            #pragma unroll
            for (int j = 0; j < 2; ++j) {
                uint32_t bx = j ? b1.x : b0.x, by = j ? b1.y : b0.y;
                uint32_t bz = j ? b1.z : b0.z, bw = j ? b1.w : b0.w;
                #pragma unroll
                for (int u = 0; u < 2; ++u) {
                    MMA(acc[qd * 2 + u][j], ah[u], bx, by);   // Ahi*Bhi
                    MMA(acc[qd * 2 + u][j], al[u], bx, by);   // Alo*Bhi
                    MMA(acc[qd * 2 + u][j], ah[u], bz, bw);   // Ahi*Blo
                }
            }
        }
        b0 = nb0; b1 = nb1;
    }
}

// ---------------- main kernel ----------------
__global__ void __launch_bounds__(512, 1) commnet_mma_kernel(
    const int*   __restrict__ ids,
    const float* __restrict__ b1,
    const float* __restrict__ b2,
    const float* __restrict__ Wd,
    const float* __restrict__ bd,
    const float* __restrict__ emb,
    float*       __restrict__ out)
{
    extern __shared__ uint8_t smraw[];
    uint2* sP  = reinterpret_cast<uint2*>(smraw + SP_OFF);     // [128][136]
    float* Sv  = reinterpret_cast<float*>(smraw + SV_OFF);     // [2][256]
    float* Tv  = reinterpret_cast<float*>(smraw + TV_OFF);     // [2][256]
    float* sWd = reinterpret_cast<float*>(smraw + WD_OFF);     // [256*16]
    float* sbd = reinterpret_cast<float*>(smraw + BD_OFF);     // [16]

    const int cta  = blockIdx.x;
    const int tid  = threadIdx.x;
    const int w    = tid >> 5;
    const int lane = tid & 31;
    const int g    = lane >> 2;
    const int t    = lane & 3;

    // ---- stage Wd/bd ----
    #pragma unroll
    for (int i = tid; i < HID * 16; i += 512) sWd[i] = Wd[i];
    if (tid < 16) sbd[tid] = bd[tid];

    // ---- gather: h0 -> split pairs in sP ----
    {
        int r  = tid >> 2;            // 0..127
        int qt = tid & 3;             // column quarter
        int aid = ids[cta * MROWS + r];
        const float4* er = reinterpret_cast<const float4*>(emb + aid * HID) + qt * 16;
        #pragma unroll
        for (int q = 0; q < 16; ++q) {
            float4 e = er[q];
            int pair = qt * 32 + q * 2;
            sP[pair * SP2 + r]       = split2(e.x, e.y);
            sP[(pair + 1) * SP2 + r] = split2(e.z, e.w);
        }
    }

    float* gp = gG0 + (size_t)cta * 32768 + tid;

    for (int step = 0; step < STEPS; ++step) {
        __syncthreads();

        // ---- Sv[b][k]: warp handles 8 pairs, lanes scan m (conflict-free) ----
        #pragma unroll
        for (int pi = 0; pi < 8; ++pi) {
            int p = w * 8 + pi;
            float2 v0 = unsplit(sP[p * SP2 + lane]);
            float2 v1 = unsplit(sP[p * SP2 + lane + 32]);
            float2 v2 = unsplit(sP[p * SP2 + lane + 64]);
            float2 v3 = unsplit(sP[p * SP2 + lane + 96]);
            float s0e = v0.x + v1.x, s0o = v0.y + v1.y;   // batch 0
            float s1e = v2.x + v3.x, s1o = v2.y + v3.y;   // batch 1
            #pragma unroll
            for (int off = 16; off; off >>= 1) {
                s0e += __shfl_xor_sync(0xFFFFFFFFu, s0e, off);
                s0o += __shfl_xor_sync(0xFFFFFFFFu, s0o, off);
                s1e += __shfl_xor_sync(0xFFFFFFFFu, s1e, off);
                s1o += __shfl_xor_sync(0xFFFFFFFFu, s1o, off);
            }
            if (lane == 0) {
                Sv[2 * p] = s0e;       Sv[2 * p + 1] = s0o;
                Sv[256 + 2 * p] = s1e; Sv[256 + 2 * p + 1] = s1o;
            }
        }
        __syncthreads();

        // ---- Tv[b][c] = b1[c] + inv * (Sv[b] @ W1b)[c]  (both batches/load) --
        #pragma unroll 2
        for (int i = 0; i < 16; ++i) {
            int c = w * 16 + i;
            float p0 = 0.f, p1 = 0.f;
            #pragma unroll
            for (int q = 0; q < 8; ++q) {
                int k = lane + 32 * q;
                float wv = __ldg(&gW1bT[c * HID + k]);
                p0 = fmaf(Sv[k], wv, p0);
                p1 = fmaf(Sv[256 + k], wv, p1);
            }
            #pragma unroll
            for (int off = 16; off; off >>= 1) {
                p0 += __shfl_xor_sync(0xFFFFFFFFu, p0, off);
                p1 += __shfl_xor_sync(0xFFFFFFFFu, p1, off);
            }
            if (lane == 0) {
                float bb = __ldg(&b1[c]);
                Tv[c]       = fmaf(p0, INVF, bb);
                Tv[256 + c] = fmaf(p1, INVF, bb);
            }
        }

        // ---- GEMM1 ----
        float acc[8][2][4];
        if (step == 0) {
            #pragma unroll
            for (int mt = 0; mt < 8; ++mt)
                #pragma unroll
                for (int j = 0; j < 2; ++j)
                    #pragma unroll
                    for (int q = 0; q < 4; ++q) acc[mt][j][q] = 0.f;
            gemm_pass(gPk[1], acc, sP, w, lane, g, t);     // G0 = h0 @ W1c
            #pragma unroll
            for (int mt = 0; mt < 8; ++mt)
                #pragma unroll
                for (int j = 0; j < 2; ++j)
                    #pragma unroll
                    for (int q = 0; q < 4; ++q)
                        gp[(((mt * 2 + j) * 4) + q) * 512] = acc[mt][j][q];
        } else {
            #pragma unroll
            for (int mt = 0; mt < 8; ++mt)
                #pragma unroll
                for (int j = 0; j < 2; ++j)
                    #pragma unroll
                    for (int q = 0; q < 4; ++q)
                        acc[mt][j][q] = gp[(((mt * 2 + j) * 4) + q) * 512];
        }
        gemm_pass(gPk[0], acc, sP, w, lane, g, t);         // += h @ W1eff
        __syncthreads();

        // ---- epilogue1: act = relu(acc+Tv) -> sP ; acc = h_old + b2 ----
        {
            const int pairb = 8 * w + t;
            const int n0b   = 16 * w + 2 * t;
            #pragma unroll
            for (int mt = 0; mt < 8; ++mt) {
                int m0   = mt * 16 + g;
                int bofs = (mt >> 2) * 256;
                #pragma unroll
                for (int j = 0; j < 2; ++j) {
                    int pair = pairb + 4 * j;
                    int n0   = n0b + 8 * j;
                    float2 hoa = unsplit(sP[pair * SP2 + m0]);
                    float2 hob = unsplit(sP[pair * SP2 + m0 + 8]);
                    float tv0 = Tv[bofs + n0], tv1 = Tv[bofs + n0 + 1];
                    float a0 = fmaxf(acc[mt][j][0] + tv0, 0.f);
                    float a1 = fmaxf(acc[mt][j][1] + tv1, 0.f);
                    float a2 = fmaxf(acc[mt][j][2] + tv0, 0.f);
                    float a3 = fmaxf(acc[mt][j][3] + tv1, 0.f);
                    sP[pair * SP2 + m0]     = split2(a0, a1);
                    sP[pair * SP2 + m0 + 8] = split2(a2, a3);
                    float bb0 = __ldg(&b2[n0]), bb1 = __ldg(&b2[n0 + 1]);
                    acc[mt][j][0] = hoa.x + bb0; acc[mt][j][1] = hoa.y + bb1;
                    acc[mt][j][2] = hob.x + bb0; acc[mt][j][3] = hob.y + bb1;
                }
            }
        }
        __syncthreads();

        // ---- GEMM2: acc += act @ W2   (acc = new h) ----
        gemm_pass(gPk[2], acc, sP, w, lane, g, t);
        __syncthreads();

        // ---- epilogue2: split new h -> sP ----
        {
            const int pairb = 8 * w + t;
            #pragma unroll
            for (int mt = 0; mt < 8; ++mt) {
                int m0 = mt * 16 + g;
                #pragma unroll
                for (int j = 0; j < 2; ++j) {
                    int pair = pairb + 4 * j;
                    sP[pair * SP2 + m0]     = split2(acc[mt][j][0], acc[mt][j][1]);
                    sP[pair * SP2 + m0 + 8] = split2(acc[mt][j][2], acc[mt][j][3]);
                }
            }
        }
    }

    __syncthreads();
    // ---- logits: out[row][:] = h[row] @ Wd + bd ----
    {
        int m = tid >> 2;               // local row 0..127
        int a = (tid & 3) * 4;          // 4 actions
        float4 s = *reinterpret_cast<const float4*>(sbd + a);
        #pragma unroll 4
        for (int pair = 0; pair < 128; ++pair) {
            float2 hp = unsplit(sP[pair * SP2 + m]);
            const float4 w0 = *reinterpret_cast<const float4*>(sWd + (2 * pair) * 16 + a);
            const float4 w1 = *reinterpret_cast<const float4*>(sWd + (2 * pair + 1) * 16 + a);
            s.x = fmaf(hp.x, w0.x, fmaf(hp.y, w1.x, s.x));
            s.y = fmaf(hp.x, w0.y, fmaf(hp.y, w1.y, s.y));
            s.z = fmaf(hp.x, w0.z, fmaf(hp.y, w1.z, s.z));
            s.w = fmaf(hp.x, w0.w, fmaf(hp.y, w1.w, s.w));
        }
        *reinterpret_cast<float4*>(out + (cta * MROWS + m) * 16 + a) = s;
    }
}

extern "C" void kernel_launch(void* const* d_in, const int* in_sizes, int n_in,
                              void* d_out, int out_size)
{
    const int*   ids = (const int*)  d_in[0];
    const float* emb = (const float*)d_in[1];
    const float* W1  = (const float*)d_in[2];
    const float* b1  = (const float*)d_in[3];
    const float* W2  = (const float*)d_in[4];
    const float* b2  = (const float*)d_in[5];
    const float* Wd  = (const float*)d_in[6];
    const float* bd  = (const float*)d_in[7];
    float* out = (float*)d_out;

    const int nCTA = in_sizes[0] / MROWS;     // 512

    prep_pack<<<192, 256>>>(W1, W2);
    prep_t<<<HID, HID>>>(W1);

    cudaFuncSetAttribute(commnet_mma_kernel,
                         cudaFuncAttributeMaxDynamicSharedMemorySize, SMEM_BYTES);
    commnet_mma_kernel<<<nCTA, 512, SMEM_BYTES>>>(ids, b1, b2, Wd, bd, emb, out);
}

// round 7
// speedup vs baseline: 1.2529x; 1.2529x over previous
#include <cuda_runtime.h>
#include <cuda_bf16.h>
#include <cstdint>

// ============================================================================
// CommNet via mma.sync m16n8k16 bf16 (compute_100-safe).
// 2 batches per CTA (M=128 rows), 512 threads = 16 warps tiled 2(m) x 8(n):
//   warp w: wm = w>>3 owns rows [64*wm, 64*wm+64)  (== batch wm)
//           wn = w&7 owns cols n in [32*wn, 32*wn+32)
// h stored in SMEM as separate hi/lo bf16x2 pair arrays, layout s*[kpair][m],
// 32-bit pitch 136 (t*8+g distinct mod 32 -> conflict-free).
// D = Ahi*Bhi + Alo*Bhi + Ahi*Blo  (fp32 accumulators).
// G0 = h0 @ W1c computed once (step 0), parked in gmem, re-added steps 1-3.
// ============================================================================

#define HID    256
#define MROWS  128
#define STEPS  4
#define INVF   (1.0f/63.0f)
#define PITCH  136             // uint32 pitch of sHi/sLo[pair][*]

// SMEM byte offsets
#define SHI_OFF  0             // 128*136*4 = 69632
#define SLO_OFF  69632
#define SV_OFF   139264        // float[2][256]
#define TV_OFF   141312        // float[2][256]
#define WD_OFF   143360        // float[256*16]
#define BD_OFF   159744        // float[16]
#define SMEM_BYTES 159808

// ---------------- device scratch ----------------
// gPk[g][(s*32+u)*32+lane] = {bh0,bh1,bl0,bl1}; g: 0=W1eff 1=W1c 2=W2
__device__ uint4 gPk[3][16384];
__device__ float gW1bT[HID * HID];          // W1b^T: [c][k]
__device__ float gG0[512 * 64 * 512];       // [cta][slot64][tid]  (64 MB)

// ---------------- fast bf16 split helpers ----------------
__device__ __forceinline__ uint32_t bf16x2_of(float lo_f, float hi_f) {
    uint32_t r;
    asm("cvt.rn.bf16x2.f32 %0, %1, %2;" : "=r"(r) : "f"(hi_f), "f"(lo_f));
    return r;
}
__device__ __forceinline__ uint2 split2(float x0, float x1) {
    uint32_t hi = bf16x2_of(x0, x1);                       // low=x0, high=x1
    float h0 = __uint_as_float(hi << 16);
    float h1 = __uint_as_float(hi & 0xFFFF0000u);
    uint32_t lo = bf16x2_of(x0 - h0, x1 - h1);
    return make_uint2(hi, lo);
}
__device__ __forceinline__ float2 unsplit(uint32_t hx, uint32_t lx) {
    float f0 = __uint_as_float(hx << 16)         + __uint_as_float(lx << 16);
    float f1 = __uint_as_float(hx & 0xFFFF0000u) + __uint_as_float(lx & 0xFFFF0000u);
    return make_float2(f0, f1);
}

#define MMA(c, a, B0, B1)                                                      \
    asm volatile("mma.sync.aligned.m16n8k16.row.col.f32.bf16.bf16.f32 "        \
                 "{%0,%1,%2,%3},{%4,%5,%6,%7},{%8,%9},{%0,%1,%2,%3};"          \
                 : "+f"((c)[0]), "+f"((c)[1]), "+f"((c)[2]), "+f"((c)[3])      \
                 : "r"((a)[0]), "r"((a)[1]), "r"((a)[2]), "r"((a)[3]),         \
                   "r"(B0), "r"(B1));

// ---------------- prep kernels (pack layout unchanged from round 5) --------
__global__ void prep_pack(const float* __restrict__ W1, const float* __restrict__ W2) {
    int idx = blockIdx.x * 256 + threadIdx.x;          // 3 * 16384
    int gm = idx >> 14;
    int r  = idx & 16383;
    int s  = r >> 10;
    int u  = (r >> 5) & 31;
    int l  = r & 31;
    int g  = l >> 2, t = l & 3;
    int n  = u * 8 + g;
    int kb = s * 16 + 2 * t;
    int ks[4] = { kb, kb + 1, kb + 8, kb + 9 };
    float v[4];
    #pragma unroll
    for (int q = 0; q < 4; ++q) {
        int k = ks[q];
        if (gm == 0)      v[q] = W1[k * HID + n] - INVF * W1[(HID + k) * HID + n];
        else if (gm == 1) v[q] = W1[(2 * HID + k) * HID + n];
        else              v[q] = W2[k * HID + n];
    }
    uint2 p0 = split2(v[0], v[1]);
    uint2 p1 = split2(v[2], v[3]);
    gPk[gm][r] = make_uint4(p0.x, p1.x, p0.y, p1.y);
}
__global__ void prep_t(const float* __restrict__ W1) {
    int c = blockIdx.x, k = threadIdx.x;
    gW1bT[c * HID + k] = W1[(HID + k) * HID + c];
}

// ---------------- GEMM pass: acc += splits(h) @ splits(B) -------------------
// Warp (wm, wn): A rows [64wm, 64wm+64), B cols n in [32wn, 32wn+32).
// acc[mt][jn][4]: mt = m16 tile (rows 64wm+16mt..), jn = n8 frag.
__device__ __forceinline__ void gemm_pass(const uint4* __restrict__ bp,
                                          float (&acc)[4][4][4],
                                          const uint32_t* __restrict__ sHi,
                                          const uint32_t* __restrict__ sLo,
                                          int wm, int wn, int lane, int g, int t) {
    const uint4* bq = bp + wn * 128 + lane;     // u = 4*wn + jn, entry u*32+lane
    uint4 cur[4];
    #pragma unroll
    for (int jn = 0; jn < 4; ++jn) cur[jn] = __ldg(bq + jn * 32);
    const int mbase = wm * 64 + g;
    #pragma unroll 2
    for (int s = 0; s < 16; ++s) {
        uint4 nxt[4];
        const int sn = (s < 15) ? s + 1 : 15;
        #pragma unroll
        for (int jn = 0; jn < 4; ++jn) nxt[jn] = __ldg(bq + sn * 1024 + jn * 32);
        const int kp0 = (s * 8 + t) * PITCH + mbase;
        const int kp2 = kp0 + 4 * PITCH;
        #pragma unroll
        for (int mt = 0; mt < 4; ++mt) {
            const int m0 = mt * 16;
            uint32_t ah[4], al[4];
            ah[0] = sHi[kp0 + m0]; ah[1] = sHi[kp0 + m0 + 8];
            ah[2] = sHi[kp2 + m0]; ah[3] = sHi[kp2 + m0 + 8];
            al[0] = sLo[kp0 + m0]; al[1] = sLo[kp0 + m0 + 8];
            al[2] = sLo[kp2 + m0]; al[3] = sLo[kp2 + m0 + 8];
            #pragma unroll
            for (int jn = 0; jn < 4; ++jn) {
                MMA(acc[mt][jn], ah, cur[jn].x, cur[jn].y);   // Ahi*Bhi
                MMA(acc[mt][jn], al, cur[jn].x, cur[jn].y);   // Alo*Bhi
                MMA(acc[mt][jn], ah, cur[jn].z, cur[jn].w);   // Ahi*Blo
            }
        }
        #pragma unroll
        for (int jn = 0; jn < 4; ++jn) cur[jn] = nxt[jn];
    }
}

// ---------------- main kernel ----------------
__global__ void __launch_bounds__(512, 1) commnet_mma_kernel(
    const int*   __restrict__ ids,
    const float* __restrict__ b1,
    const float* __restrict__ b2,
    const float* __restrict__ Wd,
    const float* __restrict__ bd,
    const float* __restrict__ emb,
    float*       __restrict__ out)
{
    extern __shared__ uint8_t smraw[];
    uint32_t* sHi = reinterpret_cast<uint32_t*>(smraw + SHI_OFF);  // [128][136]
    uint32_t* sLo = reinterpret_cast<uint32_t*>(smraw + SLO_OFF);  // [128][136]
    float*    Sv  = reinterpret_cast<float*>(smraw + SV_OFF);      // [2][256]
    float*    Tv  = reinterpret_cast<float*>(smraw + TV_OFF);      // [2][256]
    float*    sWd = reinterpret_cast<float*>(smraw + WD_OFF);      // [256*16]
    float*    sbd = reinterpret_cast<float*>(smraw + BD_OFF);      // [16]

    const int cta  = blockIdx.x;
    const int tid  = threadIdx.x;
    const int w    = tid >> 5;
    const int lane = tid & 31;
    const int g    = lane >> 2;
    const int t    = lane & 3;
    const int wm   = w >> 3;              // m-half (== local batch)
    const int wn   = w & 7;               // n-slice of 32

    // ---- stage Wd/bd ----
    #pragma unroll
    for (int i = tid; i < HID * 16; i += 512) sWd[i] = Wd[i];
    if (tid < 16) sbd[tid] = bd[tid];

    // ---- gather: h0 -> split pairs ----
    {
        int r  = tid >> 2;            // 0..127
        int qt = tid & 3;             // column quarter
        int aid = ids[cta * MROWS + r];
        const float4* er = reinterpret_cast<const float4*>(emb + aid * HID) + qt * 16;
        #pragma unroll
        for (int q = 0; q < 16; ++q) {
            float4 e = er[q];
            int pair = qt * 32 + q * 2;
            uint2 pa = split2(e.x, e.y);
            uint2 pb = split2(e.z, e.w);
            sHi[pair * PITCH + r]       = pa.x; sLo[pair * PITCH + r]       = pa.y;
            sHi[(pair + 1) * PITCH + r] = pb.x; sLo[(pair + 1) * PITCH + r] = pb.y;
        }
    }

    float* gp = gG0 + (size_t)cta * 32768 + tid;

    for (int step = 0; step < STEPS; ++step) {
        __syncthreads();

        // ---- Sv[b][k]: warp handles 8 pairs, lanes scan m (conflict-free) ----
        #pragma unroll
        for (int pi = 0; pi < 8; ++pi) {
            int p = w * 8 + pi;
            float2 v0 = unsplit(sHi[p * PITCH + lane],      sLo[p * PITCH + lane]);
            float2 v1 = unsplit(sHi[p * PITCH + lane + 32], sLo[p * PITCH + lane + 32]);
            float2 v2 = unsplit(sHi[p * PITCH + lane + 64], sLo[p * PITCH + lane + 64]);
            float2 v3 = unsplit(sHi[p * PITCH + lane + 96], sLo[p * PITCH + lane + 96]);
            float s0e = v0.x + v1.x, s0o = v0.y + v1.y;   // batch 0
            float s1e = v2.x + v3.x, s1o = v2.y + v3.y;   // batch 1
            #pragma unroll
            for (int off = 16; off; off >>= 1) {
                s0e += __shfl_xor_sync(0xFFFFFFFFu, s0e, off);
                s0o += __shfl_xor_sync(0xFFFFFFFFu, s0o, off);
                s1e += __shfl_xor_sync(0xFFFFFFFFu, s1e, off);
                s1o += __shfl_xor_sync(0xFFFFFFFFu, s1o, off);
            }
            if (lane == 0) {
                Sv[2 * p] = s0e;       Sv[2 * p + 1] = s0o;
                Sv[256 + 2 * p] = s1e; Sv[256 + 2 * p + 1] = s1o;
            }
        }
        __syncthreads();

        // ---- Tv[b][c] = b1[c] + inv * (Sv[b] @ W1b)[c] ----
        #pragma unroll 2
        for (int i = 0; i < 16; ++i) {
            int c = w * 16 + i;
            float p0 = 0.f, p1 = 0.f;
            #pragma unroll
            for (int q = 0; q < 8; ++q) {
                int k = lane + 32 * q;
                float wv = __ldg(&gW1bT[c * HID + k]);
                p0 = fmaf(Sv[k], wv, p0);
                p1 = fmaf(Sv[256 + k], wv, p1);
            }
            #pragma unroll
            for (int off = 16; off; off >>= 1) {
                p0 += __shfl_xor_sync(0xFFFFFFFFu, p0, off);
                p1 += __shfl_xor_sync(0xFFFFFFFFu, p1, off);
            }
            if (lane == 0) {
                float bb = __ldg(&b1[c]);
                Tv[c]       = fmaf(p0, INVF, bb);
                Tv[256 + c] = fmaf(p1, INVF, bb);
            }
        }

        // ---- GEMM1 ----
        float acc[4][4][4];
        if (step == 0) {
            #pragma unroll
            for (int mt = 0; mt < 4; ++mt)
                #pragma unroll
                for (int jn = 0; jn < 4; ++jn)
                    #pragma unroll
                    for (int q = 0; q < 4; ++q) acc[mt][jn][q] = 0.f;
            gemm_pass(gPk[1], acc, sHi, sLo, wm, wn, lane, g, t);   // G0 = h0@W1c
            #pragma unroll
            for (int mt = 0; mt < 4; ++mt)
                #pragma unroll
                for (int jn = 0; jn < 4; ++jn)
                    #pragma unroll
                    for (int q = 0; q < 4; ++q)
                        gp[(((mt * 4 + jn) * 4) + q) * 512] = acc[mt][jn][q];
        } else {
            #pragma unroll
            for (int mt = 0; mt < 4; ++mt)
                #pragma unroll
                for (int jn = 0; jn < 4; ++jn)
                    #pragma unroll
                    for (int q = 0; q < 4; ++q)
                        acc[mt][jn][q] = gp[(((mt * 4 + jn) * 4) + q) * 512];
        }
        gemm_pass(gPk[0], acc, sHi, sLo, wm, wn, lane, g, t);       // += h@W1eff
        __syncthreads();

        // ---- epilogue1: act = relu(acc+Tv) -> s* ; acc = h_old + b2 ----
        {
            const int bofs = wm * 256;
            #pragma unroll
            for (int mt = 0; mt < 4; ++mt) {
                const int m0 = wm * 64 + mt * 16 + g;
                #pragma unroll
                for (int jn = 0; jn < 4; ++jn) {
                    const int pair = 16 * wn + 4 * jn + t;
                    const int n0   = 32 * wn + 8 * jn + 2 * t;
                    const int i0 = pair * PITCH + m0;
                    float2 hoa = unsplit(sHi[i0],     sLo[i0]);
                    float2 hob = unsplit(sHi[i0 + 8], sLo[i0 + 8]);
                    float tv0 = Tv[bofs + n0], tv1 = Tv[bofs + n0 + 1];
                    float a0 = fmaxf(acc[mt][jn][0] + tv0, 0.f);
                    float a1 = fmaxf(acc[mt][jn][1] + tv1, 0.f);
                    float a2 = fmaxf(acc[mt][jn][2] + tv0, 0.f);
                    float a3 = fmaxf(acc[mt][jn][3] + tv1, 0.f);
                    uint2 pa = split2(a0, a1);
                    uint2 pb = split2(a2, a3);
                    sHi[i0] = pa.x;     sLo[i0] = pa.y;
                    sHi[i0 + 8] = pb.x; sLo[i0 + 8] = pb.y;
                    float bb0 = __ldg(&b2[n0]), bb1 = __ldg(&b2[n0 + 1]);
                    acc[mt][jn][0] = hoa.x + bb0; acc[mt][jn][1] = hoa.y + bb1;
                    acc[mt][jn][2] = hob.x + bb0; acc[mt][jn][3] = hob.y + bb1;
                }
            }
        }
        __syncthreads();

        // ---- GEMM2: acc += act @ W2   (acc = new h) ----
        gemm_pass(gPk[2], acc, sHi, sLo, wm, wn, lane, g, t);
        __syncthreads();

        // ---- epilogue2: split new h -> s* ----
        #pragma unroll
        for (int mt = 0; mt < 4; ++mt) {
            const int m0 = wm * 64 + mt * 16 + g;
            #pragma unroll
            for (int jn = 0; jn < 4; ++jn) {
                const int i0 = (16 * wn + 4 * jn + t) * PITCH + m0;
                uint2 pa = split2(acc[mt][jn][0], acc[mt][jn][1]);
                uint2 pb = split2(acc[mt][jn][2], acc[mt][jn][3]);
                sHi[i0] = pa.x;     sLo[i0] = pa.y;
                sHi[i0 + 8] = pb.x; sLo[i0 + 8] = pb.y;
            }
        }
    }

    __syncthreads();
    // ---- logits: out[row][:] = h[row] @ Wd + bd ----
    {
        int m = tid >> 2;               // local row 0..127
        int a = (tid & 3) * 4;          // 4 actions
        float4 s = *reinterpret_cast<const float4*>(sbd + a);
        #pragma unroll 4
        for (int pair = 0; pair < 128; ++pair) {
            float2 hp = unsplit(sHi[pair * PITCH + m], sLo[pair * PITCH + m]);
            const float4 w0 = *reinterpret_cast<const float4*>(sWd + (2 * pair) * 16 + a);
            const float4 w1 = *reinterpret_cast<const float4*>(sWd + (2 * pair + 1) * 16 + a);
            s.x = fmaf(hp.x, w0.x, fmaf(hp.y, w1.x, s.x));
            s.y = fmaf(hp.x, w0.y, fmaf(hp.y, w1.y, s.y));
            s.z = fmaf(hp.x, w0.z, fmaf(hp.y, w1.z, s.z));
            s.w = fmaf(hp.x, w0.w, fmaf(hp.y, w1.w, s.w));
        }
        *reinterpret_cast<float4*>(out + (cta * MROWS + m) * 16 + a) = s;
    }
}

extern "C" void kernel_launch(void* const* d_in, const int* in_sizes, int n_in,
                              void* d_out, int out_size)
{
    const int*   ids = (const int*)  d_in[0];
    const float* emb = (const float*)d_in[1];
    const float* W1  = (const float*)d_in[2];
    const float* b1  = (const float*)d_in[3];
    const float* W2  = (const float*)d_in[4];
    const float* b2  = (const float*)d_in[5];
    const float* Wd  = (const float*)d_in[6];
    const float* bd  = (const float*)d_in[7];
    float* out = (float*)d_out;

    const int nCTA = in_sizes[0] / MROWS;     // 512

    prep_pack<<<192, 256>>>(W1, W2);
    prep_t<<<HID, HID>>>(W1);

    cudaFuncSetAttribute(commnet_mma_kernel,
                         cudaFuncAttributeMaxDynamicSharedMemorySize, SMEM_BYTES);
    commnet_mma_kernel<<<nCTA, 512, SMEM_BYTES>>>(ids, b1, b2, Wd, bd, emb, out);
}

// round 9
// speedup vs baseline: 1.6143x; 1.2885x over previous
#include <cuda_runtime.h>
#include <cuda_fp16.h>
#include <cstdint>

// ============================================================================
// CommNet via mma.sync m16n8k16 fp16 (compute_100-safe).
// 2 batches per CTA (M=128 rows), 512 threads = 16 warps tiled 2(m) x 8(n).
// h stored in SMEM as separate hi/lo fp16x2 pair arrays, s*[kpair][m], pitch 136.
// 2-term split: D = Ahi*B + Alo*B, with A = fp16(hi)+fp16(lo) (near-exact) and
// B = single fp16 weights (RMS err ~2.8e-4, amplification ~1.2 -> ~3e-4 total).
// G0 = h0 @ W1c computed once (step 0), parked in gmem, re-added steps 1-3.
// ============================================================================

#define HID    256
#define MROWS  128
#define STEPS  4
#define INVF   (1.0f/63.0f)
#define PITCH  136             // uint32 pitch of sHi/sLo[pair][*]

// SMEM byte offsets
#define SHI_OFF  0             // 128*136*4 = 69632
#define SLO_OFF  69632
#define SV_OFF   139264        // float[2][256]
#define TV_OFF   141312        // float[2][256]
#define WD_OFF   143360        // float[256*16]
#define BD_OFF   159744        // float[16]
#define SMEM_BYTES 159808

// ---------------- device scratch ----------------
// gPk2[g][(s*32+u)*32+lane] = {b0,b1} fp16x2 B-fragments; g: 0=W1eff 1=W1c 2=W2
__device__ uint2 gPk2[3][16384];
__device__ float gW1bT[HID * HID];          // W1b^T: [c][k]
__device__ float gG0[512 * 64 * 512];       // [cta][slot64][tid]  (64 MB)

// ---------------- fp16 split helpers ----------------
__device__ __forceinline__ uint2 split2(float x0, float x1) {
    __half2 h = __float22half2_rn(make_float2(x0, x1));    // .x=low=x0
    float2 hf = __half22float2(h);
    __half2 l = __float22half2_rn(make_float2(x0 - hf.x, x1 - hf.y));
    uint2 r;
    r.x = *reinterpret_cast<uint32_t*>(&h);
    r.y = *reinterpret_cast<uint32_t*>(&l);
    return r;
}
__device__ __forceinline__ uint32_t f16x2_single(float x0, float x1) {
    __half2 h = __float22half2_rn(make_float2(x0, x1));
    return *reinterpret_cast<uint32_t*>(&h);
}
__device__ __forceinline__ float2 unsplit(uint32_t hx, uint32_t lx) {
    float2 fh = __half22float2(*reinterpret_cast<__half2*>(&hx));
    float2 fl = __half22float2(*reinterpret_cast<__half2*>(&lx));
    return make_float2(fh.x + fl.x, fh.y + fl.y);
}

#define MMA(c, a, B0, B1)                                                      \
    asm volatile("mma.sync.aligned.m16n8k16.row.col.f32.f16.f16.f32 "          \
                 "{%0,%1,%2,%3},{%4,%5,%6,%7},{%8,%9},{%0,%1,%2,%3};"          \
                 : "+f"((c)[0]), "+f"((c)[1]), "+f"((c)[2]), "+f"((c)[3])      \
                 : "r"((a)[0]), "r"((a)[1]), "r"((a)[2]), "r"((a)[3]),         \
                   "r"(B0), "r"(B1));

// ---------------- merged prep kernel ----------------
__global__ void prep_all(const float* __restrict__ W1, const float* __restrict__ W2) {
    int bid = blockIdx.x;
    if (bid < 192) {
        int idx = bid * 256 + threadIdx.x;     // 3 * 16384
        int gm = idx >> 14;
        int r  = idx & 16383;
        int s  = r >> 10;
        int u  = (r >> 5) & 31;
        int l  = r & 31;
        int g  = l >> 2, t = l & 3;
        int n  = u * 8 + g;
        int kb = s * 16 + 2 * t;
        int ks[4] = { kb, kb + 1, kb + 8, kb + 9 };
        float v[4];
        #pragma unroll
        for (int q = 0; q < 4; ++q) {
            int k = ks[q];
            if (gm == 0)      v[q] = W1[k * HID + n] - INVF * W1[(HID + k) * HID + n];
            else if (gm == 1) v[q] = W1[(2 * HID + k) * HID + n];
            else              v[q] = W2[k * HID + n];
        }
        gPk2[gm][r] = make_uint2(f16x2_single(v[0], v[1]), f16x2_single(v[2], v[3]));
    } else {
        int idx = (bid - 192) * 256 + threadIdx.x;   // 65536
        int c = idx >> 8, k = idx & 255;
        gW1bT[c * HID + k] = W1[(HID + k) * HID + c];
    }
}

// ---------------- GEMM pass: acc += (Ahi + Alo) @ B ------------------------
// Warp (wm, wn): A rows [64wm, 64wm+64), B cols n in [32wn, 32wn+32).
__device__ __forceinline__ void gemm_pass(const uint2* __restrict__ bp,
                                          float (&acc)[4][4][4],
                                          const uint32_t* __restrict__ sHi,
                                          const uint32_t* __restrict__ sLo,
                                          int wm, int wn, int lane, int g, int t) {
    const uint2* bq = bp + wn * 128 + lane;     // u = 4*wn + jn, entry u*32+lane
    uint2 cur[4];
    #pragma unroll
    for (int jn = 0; jn < 4; ++jn) cur[jn] = __ldg(bq + jn * 32);
    const int mbase = wm * 64 + g;
    #pragma unroll 2
    for (int s = 0; s < 16; ++s) {
        uint2 nxt[4];
        const int sn = (s < 15) ? s + 1 : 15;
        #pragma unroll
        for (int jn = 0; jn < 4; ++jn) nxt[jn] = __ldg(bq + sn * 1024 + jn * 32);
        const int kp0 = (s * 8 + t) * PITCH + mbase;
        const int kp2 = kp0 + 4 * PITCH;
        #pragma unroll
        for (int mt = 0; mt < 4; ++mt) {
            const int m0 = mt * 16;
            uint32_t ah[4], al[4];
            ah[0] = sHi[kp0 + m0]; ah[1] = sHi[kp0 + m0 + 8];
            ah[2] = sHi[kp2 + m0]; ah[3] = sHi[kp2 + m0 + 8];
            al[0] = sLo[kp0 + m0]; al[1] = sLo[kp0 + m0 + 8];
            al[2] = sLo[kp2 + m0]; al[3] = sLo[kp2 + m0 + 8];
            #pragma unroll
            for (int jn = 0; jn < 4; ++jn) {
                MMA(acc[mt][jn], ah, cur[jn].x, cur[jn].y);   // Ahi * B
                MMA(acc[mt][jn], al, cur[jn].x, cur[jn].y);   // Alo * B
            }
        }
        #pragma unroll
        for (int jn = 0; jn < 4; ++jn) cur[jn] = nxt[jn];
    }
}

// ---------------- main kernel ----------------
__global__ void __launch_bounds__(512, 1) commnet_mma_kernel(
    const int*   __restrict__ ids,
    const float* __restrict__ b1,
    const float* __restrict__ b2,
    const float* __restrict__ Wd,
    const float* __restrict__ bd,
    const float* __restrict__ emb,
    float*       __restrict__ out)
{
    extern __shared__ uint8_t smraw[];
    uint32_t* sHi = reinterpret_cast<uint32_t*>(smraw + SHI_OFF);  // [128][136]
    uint32_t* sLo = reinterpret_cast<uint32_t*>(smraw + SLO_OFF);  // [128][136]
    float*    Sv  = reinterpret_cast<float*>(smraw + SV_OFF);      // [2][256]
    float*    Tv  = reinterpret_cast<float*>(smraw + TV_OFF);      // [2][256]
    float*    sWd = reinterpret_cast<float*>(smraw + WD_OFF);      // [256*16]
    float*    sbd = reinterpret_cast<float*>(smraw + BD_OFF);      // [16]

    const int cta  = blockIdx.x;
    const int tid  = threadIdx.x;
    const int w    = tid >> 5;
    const int lane = tid & 31;
    const int g    = lane >> 2;
    const int t    = lane & 3;
    const int wm   = w >> 3;              // m-half (== local batch)
    const int wn   = w & 7;               // n-slice of 32

    // ---- stage Wd/bd ----
    #pragma unroll
    for (int i = tid; i < HID * 16; i += 512) sWd[i] = Wd[i];
    if (tid < 16) sbd[tid] = bd[tid];

    // ---- gather: h0 -> split pairs ----
    {
        int r  = tid >> 2;            // 0..127
        int qt = tid & 3;             // column quarter
        int aid = ids[cta * MROWS + r];
        const float4* er = reinterpret_cast<const float4*>(emb + aid * HID) + qt * 16;
        #pragma unroll
        for (int q = 0; q < 16; ++q) {
            float4 e = er[q];
            int pair = qt * 32 + q * 2;
            uint2 pa = split2(e.x, e.y);
            uint2 pb = split2(e.z, e.w);
            sHi[pair * PITCH + r]       = pa.x; sLo[pair * PITCH + r]       = pa.y;
            sHi[(pair + 1) * PITCH + r] = pb.x; sLo[(pair + 1) * PITCH + r] = pb.y;
        }
    }

    float* gp = gG0 + (size_t)cta * 32768 + tid;

    for (int step = 0; step < STEPS; ++step) {
        __syncthreads();

        // ---- Sv[b][k]: warp handles 8 pairs, lanes scan m (conflict-free) ----
        #pragma unroll
        for (int pi = 0; pi < 8; ++pi) {
            int p = w * 8 + pi;
            float2 v0 = unsplit(sHi[p * PITCH + lane],      sLo[p * PITCH + lane]);
            float2 v1 = unsplit(sHi[p * PITCH + lane + 32], sLo[p * PITCH + lane + 32]);
            float2 v2 = unsplit(sHi[p * PITCH + lane + 64], sLo[p * PITCH + lane + 64]);
            float2 v3 = unsplit(sHi[p * PITCH + lane + 96], sLo[p * PITCH + lane + 96]);
            float s0e = v0.x + v1.x, s0o = v0.y + v1.y;   // batch 0
            float s1e = v2.x + v3.x, s1o = v2.y + v3.y;   // batch 1
            #pragma unroll
            for (int off = 16; off; off >>= 1) {
                s0e += __shfl_xor_sync(0xFFFFFFFFu, s0e, off);
                s0o += __shfl_xor_sync(0xFFFFFFFFu, s0o, off);
                s1e += __shfl_xor_sync(0xFFFFFFFFu, s1e, off);
                s1o += __shfl_xor_sync(0xFFFFFFFFu, s1o, off);
            }
            if (lane == 0) {
                Sv[2 * p] = s0e;       Sv[2 * p + 1] = s0o;
                Sv[256 + 2 * p] = s1e; Sv[256 + 2 * p + 1] = s1o;
            }
        }
        __syncthreads();

        // ---- Tv[b][c] = b1[c] + inv * (Sv[b] @ W1b)[c] ----
        #pragma unroll 2
        for (int i = 0; i < 16; ++i) {
            int c = w * 16 + i;
            float p0 = 0.f, p1 = 0.f;
            #pragma unroll
            for (int q = 0; q < 8; ++q) {
                int k = lane + 32 * q;
                float wv = __ldg(&gW1bT[c * HID + k]);
                p0 = fmaf(Sv[k], wv, p0);
                p1 = fmaf(Sv[256 + k], wv, p1);
            }
            #pragma unroll
            for (int off = 16; off; off >>= 1) {
                p0 += __shfl_xor_sync(0xFFFFFFFFu, p0, off);
                p1 += __shfl_xor_sync(0xFFFFFFFFu, p1, off);
            }
            if (lane == 0) {
                float bb = __ldg(&b1[c]);
                Tv[c]       = fmaf(p0, INVF, bb);
                Tv[256 + c] = fmaf(p1, INVF, bb);
            }
        }

        // ---- GEMM1 ----
        float acc[4][4][4];
        if (step == 0) {
            #pragma unroll
            for (int mt = 0; mt < 4; ++mt)
                #pragma unroll
                for (int jn = 0; jn < 4; ++jn)
                    #pragma unroll
                    for (int q = 0; q < 4; ++q) acc[mt][jn][q] = 0.f;
            gemm_pass(gPk2[1], acc, sHi, sLo, wm, wn, lane, g, t);  // G0 = h0@W1c
            #pragma unroll
            for (int mt = 0; mt < 4; ++mt)
                #pragma unroll
                for (int jn = 0; jn < 4; ++jn)
                    #pragma unroll
                    for (int q = 0; q < 4; ++q)
                        gp[(((mt * 4 + jn) * 4) + q) * 512] = acc[mt][jn][q];
        } else {
            #pragma unroll
            for (int mt = 0; mt < 4; ++mt)
                #pragma unroll
                for (int jn = 0; jn < 4; ++jn)
                    #pragma unroll
                    for (int q = 0; q < 4; ++q)
                        acc[mt][jn][q] = gp[(((mt * 4 + jn) * 4) + q) * 512];
        }
        gemm_pass(gPk2[0], acc, sHi, sLo, wm, wn, lane, g, t);      // += h@W1eff
        __syncthreads();

        // ---- epilogue1: act = relu(acc+Tv) -> s* ; acc = h_old + b2 ----
        {
            const int bofs = wm * 256;
            #pragma unroll
            for (int mt = 0; mt < 4; ++mt) {
                const int m0 = wm * 64 + mt * 16 + g;
                #pragma unroll
                for (int jn = 0; jn < 4; ++jn) {
                    const int pair = 16 * wn + 4 * jn + t;
                    const int n0   = 32 * wn + 8 * jn + 2 * t;
                    const int i0 = pair * PITCH + m0;
                    float2 hoa = unsplit(sHi[i0],     sLo[i0]);
                    float2 hob = unsplit(sHi[i0 + 8], sLo[i0 + 8]);
                    float tv0 = Tv[bofs + n0], tv1 = Tv[bofs + n0 + 1];
                    float a0 = fmaxf(acc[mt][jn][0] + tv0, 0.f);
                    float a1 = fmaxf(acc[mt][jn][1] + tv1, 0.f);
                    float a2 = fmaxf(acc[mt][jn][2] + tv0, 0.f);
                    float a3 = fmaxf(acc[mt][jn][3] + tv1, 0.f);
                    uint2 pa = split2(a0, a1);
                    uint2 pb = split2(a2, a3);
                    sHi[i0] = pa.x;     sLo[i0] = pa.y;
                    sHi[i0 + 8] = pb.x; sLo[i0 + 8] = pb.y;
                    float bb0 = __ldg(&b2[n0]), bb1 = __ldg(&b2[n0 + 1]);
                    acc[mt][jn][0] = hoa.x + bb0; acc[mt][jn][1] = hoa.y + bb1;
                    acc[mt][jn][2] = hob.x + bb0; acc[mt][jn][3] = hob.y + bb1;
                }
            }
        }
        __syncthreads();

        // ---- GEMM2: acc += act @ W2   (acc = new h) ----
        gemm_pass(gPk2[2], acc, sHi, sLo, wm, wn, lane, g, t);
        __syncthreads();

        // ---- epilogue2: split new h -> s* ----
        #pragma unroll
        for (int mt = 0; mt < 4; ++mt) {
            const int m0 = wm * 64 + mt * 16 + g;
            #pragma unroll
            for (int jn = 0; jn < 4; ++jn) {
                const int i0 = (16 * wn + 4 * jn + t) * PITCH + m0;
                uint2 pa = split2(acc[mt][jn][0], acc[mt][jn][1]);
                uint2 pb = split2(acc[mt][jn][2], acc[mt][jn][3]);
                sHi[i0] = pa.x;     sLo[i0] = pa.y;
                sHi[i0 + 8] = pb.x; sLo[i0 + 8] = pb.y;
            }
        }
    }

    __syncthreads();
    // ---- logits: out[row][:] = h[row] @ Wd + bd ----
    {
        int m = tid >> 2;               // local row 0..127
        int a = (tid & 3) * 4;          // 4 actions
        float4 s = *reinterpret_cast<const float4*>(sbd + a);
        #pragma unroll 4
        for (int pair = 0; pair < 128; ++pair) {
            float2 hp = unsplit(sHi[pair * PITCH + m], sLo[pair * PITCH + m]);
            const float4 w0 = *reinterpret_cast<const float4*>(sWd + (2 * pair) * 16 + a);
            const float4 w1 = *reinterpret_cast<const float4*>(sWd + (2 * pair + 1) * 16 + a);
            s.x = fmaf(hp.x, w0.x, fmaf(hp.y, w1.x, s.x));
            s.y = fmaf(hp.x, w0.y, fmaf(hp.y, w1.y, s.y));
            s.z = fmaf(hp.x, w0.z, fmaf(hp.y, w1.z, s.z));
            s.w = fmaf(hp.x, w0.w, fmaf(hp.y, w1.w, s.w));
        }
        *reinterpret_cast<float4*>(out + (cta * MROWS + m) * 16 + a) = s;
    }
}

extern "C" void kernel_launch(void* const* d_in, const int* in_sizes, int n_in,
                              void* d_out, int out_size)
{
    const int*   ids = (const int*)  d_in[0];
    const float* emb = (const float*)d_in[1];
    const float* W1  = (const float*)d_in[2];
    const float* b1  = (const float*)d_in[3];
    const float* W2  = (const float*)d_in[4];
    const float* b2  = (const float*)d_in[5];
    const float* Wd  = (const float*)d_in[6];
    const float* bd  = (const float*)d_in[7];
    float* out = (float*)d_out;

    const int nCTA = in_sizes[0] / MROWS;     // 512

    prep_all<<<448, 256>>>(W1, W2);

    cudaFuncSetAttribute(commnet_mma_kernel,
                         cudaFuncAttributeMaxDynamicSharedMemorySize, SMEM_BYTES);
    commnet_mma_kernel<<<nCTA, 512, SMEM_BYTES>>>(ids, b1, b2, Wd, bd, emb, out);
}

// round 10
// speedup vs baseline: 1.6563x; 1.0260x over previous
#include <cuda_runtime.h>
#include <cuda_fp16.h>
#include <cstdint>

// ============================================================================
// CommNet via mma.sync m16n8k16 fp16 (compute_100-safe).
// 1 batch per CTA (M=64), grid=1024, 512 threads = 16 warps tiled 2(m) x 8(n):
//   wm = w>>3 owns rows [32wm, 32wm+32); wn = w&7 owns cols [32wn, 32wn+32).
// Sized for 2 CTAs/SM (SMEM ~92KB, 64-reg target) so a co-resident CTA's GEMM
// fills this CTA's Sv/Tv/epilogue gaps (round 9: tensor pipe idle 57%).
// h in SMEM as separate hi/lo fp16x2 pair arrays s*[kpair][m], pitch 72.
// 2-term split: D = Ahi*B + Alo*B  (B single fp16; measured rel_err ~1e-4).
// G0 = h0 @ W1c computed once (step 0), parked in gmem, re-added steps 1-3.
// ============================================================================

#define HID    256
#define MAG    64
#define STEPS  4
#define INVF   (1.0f/63.0f)
#define PITCH  72              // uint32 pitch of sHi/sLo[pair][*] (conflict-free)

// SMEM byte offsets
#define SHI_OFF  0             // 128*72*4 = 36864
#define SLO_OFF  36864
#define SV_OFF   73728         // float[256]
#define TV_OFF   74752         // float[256]
#define WD_OFF   75776         // float[256*16]
#define BD_OFF   92160         // float[16]
#define SMEM_BYTES 92224

// ---------------- device scratch ----------------
// gPk2[g][(s*32+u)*32+lane] = {b0,b1} fp16x2 B-fragments; g: 0=W1eff 1=W1c 2=W2
__device__ uint2 gPk2[3][16384];
__device__ float gW1bT[HID * HID];          // W1b^T: [c][k]
__device__ float gG0[1024 * 32 * 512];      // [cta][slot32][tid]  (64 MB)

// ---------------- fp16 split helpers ----------------
__device__ __forceinline__ uint2 split2(float x0, float x1) {
    __half2 h = __float22half2_rn(make_float2(x0, x1));    // .x=low=x0
    float2 hf = __half22float2(h);
    __half2 l = __float22half2_rn(make_float2(x0 - hf.x, x1 - hf.y));
    uint2 r;
    r.x = *reinterpret_cast<uint32_t*>(&h);
    r.y = *reinterpret_cast<uint32_t*>(&l);
    return r;
}
__device__ __forceinline__ uint32_t f16x2_single(float x0, float x1) {
    __half2 h = __float22half2_rn(make_float2(x0, x1));
    return *reinterpret_cast<uint32_t*>(&h);
}
__device__ __forceinline__ float2 unsplit(uint32_t hx, uint32_t lx) {
    float2 fh = __half22float2(*reinterpret_cast<__half2*>(&hx));
    float2 fl = __half22float2(*reinterpret_cast<__half2*>(&lx));
    return make_float2(fh.x + fl.x, fh.y + fl.y);
}

#define MMA(c, a, B0, B1)                                                      \
    asm volatile("mma.sync.aligned.m16n8k16.row.col.f32.f16.f16.f32 "          \
                 "{%0,%1,%2,%3},{%4,%5,%6,%7},{%8,%9},{%0,%1,%2,%3};"          \
                 : "+f"((c)[0]), "+f"((c)[1]), "+f"((c)[2]), "+f"((c)[3])      \
                 : "r"((a)[0]), "r"((a)[1]), "r"((a)[2]), "r"((a)[3]),         \
                   "r"(B0), "r"(B1));

// ---------------- merged prep kernel ----------------
__global__ void prep_all(const float* __restrict__ W1, const float* __restrict__ W2) {
    int bid = blockIdx.x;
    if (bid < 192) {
        int idx = bid * 256 + threadIdx.x;     // 3 * 16384
        int gm = idx >> 14;
        int r  = idx & 16383;
        int s  = r >> 10;
        int u  = (r >> 5) & 31;
        int l  = r & 31;
        int g  = l >> 2, t = l & 3;
        int n  = u * 8 + g;
        int kb = s * 16 + 2 * t;
        int ks[4] = { kb, kb + 1, kb + 8, kb + 9 };
        float v[4];
        #pragma unroll
        for (int q = 0; q < 4; ++q) {
            int k = ks[q];
            if (gm == 0)      v[q] = W1[k * HID + n] - INVF * W1[(HID + k) * HID + n];
            else if (gm == 1) v[q] = W1[(2 * HID + k) * HID + n];
            else              v[q] = W2[k * HID + n];
        }
        gPk2[gm][r] = make_uint2(f16x2_single(v[0], v[1]), f16x2_single(v[2], v[3]));
    } else {
        int idx = (bid - 192) * 256 + threadIdx.x;   // 65536
        int c = idx >> 8, k = idx & 255;
        gW1bT[c * HID + k] = W1[(HID + k) * HID + c];
    }
}

// ---------------- GEMM pass: acc += (Ahi + Alo) @ B ------------------------
// Warp (wm, wn): A rows [32wm, 32wm+32), B cols n in [32wn, 32wn+32).
// No B software-prefetch: 2 CTAs/SM (32 warps) hide the L2 latency.
__device__ __forceinline__ void gemm_pass(const uint2* __restrict__ bp,
                                          float (&acc)[2][4][4],
                                          const uint32_t* __restrict__ sHi,
                                          const uint32_t* __restrict__ sLo,
                                          int wm, int wn, int lane, int g, int t) {
    const uint2* bq = bp + wn * 128 + lane;     // u = 4*wn + jn, entry u*32+lane
    const int mbase = wm * 32 + g;
    #pragma unroll 2
    for (int s = 0; s < 16; ++s) {
        uint2 cur[4];
        #pragma unroll
        for (int jn = 0; jn < 4; ++jn) cur[jn] = __ldg(bq + s * 1024 + jn * 32);
        const int kp0 = (s * 8 + t) * PITCH + mbase;
        const int kp2 = kp0 + 4 * PITCH;
        #pragma unroll
        for (int mt = 0; mt < 2; ++mt) {
            const int m0 = mt * 16;
            uint32_t ah[4], al[4];
            ah[0] = sHi[kp0 + m0]; ah[1] = sHi[kp0 + m0 + 8];
            ah[2] = sHi[kp2 + m0]; ah[3] = sHi[kp2 + m0 + 8];
            al[0] = sLo[kp0 + m0]; al[1] = sLo[kp0 + m0 + 8];
            al[2] = sLo[kp2 + m0]; al[3] = sLo[kp2 + m0 + 8];
            #pragma unroll
            for (int jn = 0; jn < 4; ++jn) {
                MMA(acc[mt][jn], ah, cur[jn].x, cur[jn].y);   // Ahi * B
                MMA(acc[mt][jn], al, cur[jn].x, cur[jn].y);   // Alo * B
            }
        }
    }
}

// ---------------- main kernel ----------------
__global__ void __launch_bounds__(512, 2) commnet_mma_kernel(
    const int*   __restrict__ ids,
    const float* __restrict__ b1,
    const float* __restrict__ b2,
    const float* __restrict__ Wd,
    const float* __restrict__ bd,
    const float* __restrict__ emb,
    float*       __restrict__ out)
{
    extern __shared__ uint8_t smraw[];
    uint32_t* sHi = reinterpret_cast<uint32_t*>(smraw + SHI_OFF);  // [128][72]
    uint32_t* sLo = reinterpret_cast<uint32_t*>(smraw + SLO_OFF);  // [128][72]
    float*    Sv  = reinterpret_cast<float*>(smraw + SV_OFF);      // [256]
    float*    Tv  = reinterpret_cast<float*>(smraw + TV_OFF);      // [256]
    float*    sWd = reinterpret_cast<float*>(smraw + WD_OFF);      // [256*16]
    float*    sbd = reinterpret_cast<float*>(smraw + BD_OFF);      // [16]

    const int cta  = blockIdx.x;
    const int tid  = threadIdx.x;
    const int w    = tid >> 5;
    const int lane = tid & 31;
    const int g    = lane >> 2;
    const int t    = lane & 3;
    const int wm   = w >> 3;              // m-half: rows [32wm, 32wm+32)
    const int wn   = w & 7;               // n-slice of 32

    // ---- stage Wd/bd ----
    #pragma unroll
    for (int i = tid; i < HID * 16; i += 512) sWd[i] = Wd[i];
    if (tid < 16) sbd[tid] = bd[tid];

    // ---- gather: h0 -> split pairs ----
    {
        int r  = tid >> 3;            // row 0..63
        int qt = tid & 7;             // column eighth
        int aid = ids[cta * MAG + r];
        const float4* er = reinterpret_cast<const float4*>(emb + aid * HID);
        #pragma unroll
        for (int q = 0; q < 8; ++q) {
            int f = qt * 8 + q;       // float4 index 0..63
            float4 e = er[f];
            int pair = 2 * f;
            uint2 pa = split2(e.x, e.y);
            uint2 pb = split2(e.z, e.w);
            sHi[pair * PITCH + r]       = pa.x; sLo[pair * PITCH + r]       = pa.y;
            sHi[(pair + 1) * PITCH + r] = pb.x; sLo[(pair + 1) * PITCH + r] = pb.y;
        }
    }

    float* gp = gG0 + (size_t)cta * 16384 + tid;

    for (int step = 0; step < STEPS; ++step) {
        __syncthreads();

        // ---- Sv[k] = sum_m h[m][k]: warp handles 8 pairs, lanes scan m ----
        #pragma unroll
        for (int pi = 0; pi < 8; ++pi) {
            int p = w * 8 + pi;
            float2 v0 = unsplit(sHi[p * PITCH + lane],      sLo[p * PITCH + lane]);
            float2 v1 = unsplit(sHi[p * PITCH + lane + 32], sLo[p * PITCH + lane + 32]);
            float se = v0.x + v1.x, so = v0.y + v1.y;
            #pragma unroll
            for (int off = 16; off; off >>= 1) {
                se += __shfl_xor_sync(0xFFFFFFFFu, se, off);
                so += __shfl_xor_sync(0xFFFFFFFFu, so, off);
            }
            if (lane == 0) { Sv[2 * p] = se; Sv[2 * p + 1] = so; }
        }
        __syncthreads();

        // ---- Tv[c] = b1[c] + inv * (Sv @ W1b)[c] ----
        #pragma unroll 2
        for (int i = 0; i < 16; ++i) {
            int c = w * 16 + i;
            float p0 = 0.f;
            #pragma unroll
            for (int q = 0; q < 8; ++q) {
                int k = lane + 32 * q;
                p0 = fmaf(Sv[k], __ldg(&gW1bT[c * HID + k]), p0);
            }
            #pragma unroll
            for (int off = 16; off; off >>= 1)
                p0 += __shfl_xor_sync(0xFFFFFFFFu, p0, off);
            if (lane == 0) Tv[c] = fmaf(p0, INVF, __ldg(&b1[c]));
        }

        // ---- GEMM1 ----
        float acc[2][4][4];
        if (step == 0) {
            #pragma unroll
            for (int mt = 0; mt < 2; ++mt)
                #pragma unroll
                for (int jn = 0; jn < 4; ++jn)
                    #pragma unroll
                    for (int q = 0; q < 4; ++q) acc[mt][jn][q] = 0.f;
            gemm_pass(gPk2[1], acc, sHi, sLo, wm, wn, lane, g, t);  // G0 = h0@W1c
            #pragma unroll
            for (int mt = 0; mt < 2; ++mt)
                #pragma unroll
                for (int jn = 0; jn < 4; ++jn)
                    #pragma unroll
                    for (int q = 0; q < 4; ++q)
                        gp[(((mt * 4 + jn) * 4) + q) * 512] = acc[mt][jn][q];
        } else {
            #pragma unroll
            for (int mt = 0; mt < 2; ++mt)
                #pragma unroll
                for (int jn = 0; jn < 4; ++jn)
                    #pragma unroll
                    for (int q = 0; q < 4; ++q)
                        acc[mt][jn][q] = gp[(((mt * 4 + jn) * 4) + q) * 512];
        }
        gemm_pass(gPk2[0], acc, sHi, sLo, wm, wn, lane, g, t);      // += h@W1eff
        __syncthreads();

        // ---- epilogue1: act = relu(acc+Tv) -> s* ; acc = h_old + b2 ----
        #pragma unroll
        for (int mt = 0; mt < 2; ++mt) {
            const int m0 = wm * 32 + mt * 16 + g;
            #pragma unroll
            for (int jn = 0; jn < 4; ++jn) {
                const int pair = 16 * wn + 4 * jn + t;
                const int n0   = 32 * wn + 8 * jn + 2 * t;
                const int i0 = pair * PITCH + m0;
                float2 hoa = unsplit(sHi[i0],     sLo[i0]);
                float2 hob = unsplit(sHi[i0 + 8], sLo[i0 + 8]);
                float tv0 = Tv[n0], tv1 = Tv[n0 + 1];
                float a0 = fmaxf(acc[mt][jn][0] + tv0, 0.f);
                float a1 = fmaxf(acc[mt][jn][1] + tv1, 0.f);
                float a2 = fmaxf(acc[mt][jn][2] + tv0, 0.f);
                float a3 = fmaxf(acc[mt][jn][3] + tv1, 0.f);
                uint2 pa = split2(a0, a1);
                uint2 pb = split2(a2, a3);
                sHi[i0] = pa.x;     sLo[i0] = pa.y;
                sHi[i0 + 8] = pb.x; sLo[i0 + 8] = pb.y;
                float bb0 = __ldg(&b2[n0]), bb1 = __ldg(&b2[n0 + 1]);
                acc[mt][jn][0] = hoa.x + bb0; acc[mt][jn][1] = hoa.y + bb1;
                acc[mt][jn][2] = hob.x + bb0; acc[mt][jn][3] = hob.y + bb1;
            }
        }
        __syncthreads();

        // ---- GEMM2: acc += act @ W2   (acc = new h) ----
        gemm_pass(gPk2[2], acc, sHi, sLo, wm, wn, lane, g, t);
        __syncthreads();

        // ---- epilogue2: split new h -> s* ----
        #pragma unroll
        for (int mt = 0; mt < 2; ++mt) {
            const int m0 = wm * 32 + mt * 16 + g;
            #pragma unroll
            for (int jn = 0; jn < 4; ++jn) {
                const int i0 = (16 * wn + 4 * jn + t) * PITCH + m0;
                uint2 pa = split2(acc[mt][jn][0], acc[mt][jn][1]);
                uint2 pb = split2(acc[mt][jn][2], acc[mt][jn][3]);
                sHi[i0] = pa.x;     sLo[i0] = pa.y;
                sHi[i0 + 8] = pb.x; sLo[i0 + 8] = pb.y;
            }
        }
    }

    __syncthreads();
    // ---- logits: out[row][:] = h[row] @ Wd + bd ----
    {
        int m = tid >> 3;               // local row 0..63
        int a = (tid & 7) * 2;          // 2 actions each
        float s0 = sbd[a], s1 = sbd[a + 1];
        #pragma unroll 4
        for (int pair = 0; pair < 128; ++pair) {
            float2 hp = unsplit(sHi[pair * PITCH + m], sLo[pair * PITCH + m]);
            const float2 w0 = *reinterpret_cast<const float2*>(sWd + (2 * pair) * 16 + a);
            const float2 w1 = *reinterpret_cast<const float2*>(sWd + (2 * pair + 1) * 16 + a);
            s0 = fmaf(hp.x, w0.x, fmaf(hp.y, w1.x, s0));
            s1 = fmaf(hp.x, w0.y, fmaf(hp.y, w1.y, s1));
        }
        *reinterpret_cast<float2*>(out + (cta * MAG + m) * 16 + a) = make_float2(s0, s1);
    }
}

extern "C" void kernel_launch(void* const* d_in, const int* in_sizes, int n_in,
                              void* d_out, int out_size)
{
    const int*   ids = (const int*)  d_in[0];
    const float* emb = (const float*)d_in[1];
    const float* W1  = (const float*)d_in[2];
    const float* b1  = (const float*)d_in[3];
    const float* W2  = (const float*)d_in[4];
    const float* b2  = (const float*)d_in[5];
    const float* Wd  = (const float*)d_in[6];
    const float* bd  = (const float*)d_in[7];
    float* out = (float*)d_out;

    const int nCTA = in_sizes[0] / MAG;       // 1024

    prep_all<<<448, 256>>>(W1, W2);

    cudaFuncSetAttribute(commnet_mma_kernel,
                         cudaFuncAttributeMaxDynamicSharedMemorySize, SMEM_BYTES);
    commnet_mma_kernel<<<nCTA, 512, SMEM_BYTES>>>(ids, b1, b2, Wd, bd, emb, out);
}

// round 11
// speedup vs baseline: 2.1687x; 1.3094x over previous
#include <cuda_runtime.h>
#include <cuda_fp16.h>
#include <cstdint>

// ============================================================================
// CommNet via mma.sync m16n8k16 fp16 (compute_100-safe).
// 1 batch per CTA (M=64), grid=1024, 512 threads = 16 warps tiled 2(m) x 8(n).
// 2 CTAs/SM (SMEM ~92KB, 64 regs). h kept in SMEM as hi/lo fp16x2 split pairs
// (near-exact state), but MMAs consume A as single fp16 (hi only):
//   D = Ahi * B      (B single fp16)
// Round-10 ncu showed L1tex=79.4% (wavefront-bound): dropping the Alo term
// halves both MMA work and A-fragment LDS traffic. Error budget (calibrated):
// B-rounding alone measured 1.05e-4; +A-rounding predicted ~2e-4 (<1e-3).
// G0 = h0 @ W1c computed once (step 0), parked in gmem, re-added steps 1-3.
// ============================================================================

#define HID    256
#define MAG    64
#define STEPS  4
#define INVF   (1.0f/63.0f)
#define PITCH  72              // uint32 pitch of sHi/sLo[pair][*] (conflict-free)

// SMEM byte offsets
#define SHI_OFF  0             // 128*72*4 = 36864
#define SLO_OFF  36864
#define SV_OFF   73728         // float[256]
#define TV_OFF   74752         // float[256]
#define WD_OFF   75776         // float[256*16]
#define BD_OFF   92160         // float[16]
#define SMEM_BYTES 92224

// ---------------- device scratch ----------------
// gPk2[g][(s*32+u)*32+lane] = {b0,b1} fp16x2 B-fragments; g: 0=W1eff 1=W1c 2=W2
__device__ uint2 gPk2[3][16384];
__device__ float gW1bT[HID * HID];          // W1b^T: [c][k]
__device__ float gG0[1024 * 32 * 512];      // [cta][slot32][tid]  (64 MB)

// ---------------- fp16 split helpers ----------------
__device__ __forceinline__ uint2 split2(float x0, float x1) {
    __half2 h = __float22half2_rn(make_float2(x0, x1));    // .x=low=x0
    float2 hf = __half22float2(h);
    __half2 l = __float22half2_rn(make_float2(x0 - hf.x, x1 - hf.y));
    uint2 r;
    r.x = *reinterpret_cast<uint32_t*>(&h);
    r.y = *reinterpret_cast<uint32_t*>(&l);
    return r;
}
__device__ __forceinline__ uint32_t f16x2_single(float x0, float x1) {
    __half2 h = __float22half2_rn(make_float2(x0, x1));
    return *reinterpret_cast<uint32_t*>(&h);
}
__device__ __forceinline__ float2 unsplit(uint32_t hx, uint32_t lx) {
    float2 fh = __half22float2(*reinterpret_cast<__half2*>(&hx));
    float2 fl = __half22float2(*reinterpret_cast<__half2*>(&lx));
    return make_float2(fh.x + fl.x, fh.y + fl.y);
}

#define MMA(c, a, B0, B1)                                                      \
    asm volatile("mma.sync.aligned.m16n8k16.row.col.f32.f16.f16.f32 "          \
                 "{%0,%1,%2,%3},{%4,%5,%6,%7},{%8,%9},{%0,%1,%2,%3};"          \
                 : "+f"((c)[0]), "+f"((c)[1]), "+f"((c)[2]), "+f"((c)[3])      \
                 : "r"((a)[0]), "r"((a)[1]), "r"((a)[2]), "r"((a)[3]),         \
                   "r"(B0), "r"(B1));

// ---------------- merged prep kernel ----------------
__global__ void prep_all(const float* __restrict__ W1, const float* __restrict__ W2) {
    int bid = blockIdx.x;
    if (bid < 192) {
        int idx = bid * 256 + threadIdx.x;     // 3 * 16384
        int gm = idx >> 14;
        int r  = idx & 16383;
        int s  = r >> 10;
        int u  = (r >> 5) & 31;
        int l  = r & 31;
        int g  = l >> 2, t = l & 3;
        int n  = u * 8 + g;
        int kb = s * 16 + 2 * t;
        int ks[4] = { kb, kb + 1, kb + 8, kb + 9 };
        float v[4];
        #pragma unroll
        for (int q = 0; q < 4; ++q) {
            int k = ks[q];
            if (gm == 0)      v[q] = W1[k * HID + n] - INVF * W1[(HID + k) * HID + n];
            else if (gm == 1) v[q] = W1[(2 * HID + k) * HID + n];
            else              v[q] = W2[k * HID + n];
        }
        gPk2[gm][r] = make_uint2(f16x2_single(v[0], v[1]), f16x2_single(v[2], v[3]));
    } else {
        int idx = (bid - 192) * 256 + threadIdx.x;   // 65536
        int c = idx >> 8, k = idx & 255;
        gW1bT[c * HID + k] = W1[(HID + k) * HID + c];
    }
}

// ---------------- GEMM pass: acc += Ahi @ B --------------------------------
// Warp (wm, wn): A rows [32wm, 32wm+32), B cols n in [32wn, 32wn+32).
// Single-term fp16 MMA: only the hi split of A is read (halved LDS + MMAs).
__device__ __forceinline__ void gemm_pass(const uint2* __restrict__ bp,
                                          float (&acc)[2][4][4],
                                          const uint32_t* __restrict__ sHi,
                                          int wm, int wn, int lane, int g, int t) {
    const uint2* bq = bp + wn * 128 + lane;     // u = 4*wn + jn, entry u*32+lane
    const int mbase = wm * 32 + g;
    #pragma unroll 2
    for (int s = 0; s < 16; ++s) {
        uint2 cur[4];
        #pragma unroll
        for (int jn = 0; jn < 4; ++jn) cur[jn] = __ldg(bq + s * 1024 + jn * 32);
        const int kp0 = (s * 8 + t) * PITCH + mbase;
        const int kp2 = kp0 + 4 * PITCH;
        #pragma unroll
        for (int mt = 0; mt < 2; ++mt) {
            const int m0 = mt * 16;
            uint32_t ah[4];
            ah[0] = sHi[kp0 + m0]; ah[1] = sHi[kp0 + m0 + 8];
            ah[2] = sHi[kp2 + m0]; ah[3] = sHi[kp2 + m0 + 8];
            #pragma unroll
            for (int jn = 0; jn < 4; ++jn) {
                MMA(acc[mt][jn], ah, cur[jn].x, cur[jn].y);   // Ahi * B
            }
        }
    }
}

// ---------------- main kernel ----------------
__global__ void __launch_bounds__(512, 2) commnet_mma_kernel(
    const int*   __restrict__ ids,
    const float* __restrict__ b1,
    const float* __restrict__ b2,
    const float* __restrict__ Wd,
    const float* __restrict__ bd,
    const float* __restrict__ emb,
    float*       __restrict__ out)
{
    extern __shared__ uint8_t smraw[];
    uint32_t* sHi = reinterpret_cast<uint32_t*>(smraw + SHI_OFF);  // [128][72]
    uint32_t* sLo = reinterpret_cast<uint32_t*>(smraw + SLO_OFF);  // [128][72]
    float*    Sv  = reinterpret_cast<float*>(smraw + SV_OFF);      // [256]
    float*    Tv  = reinterpret_cast<float*>(smraw + TV_OFF);      // [256]
    float*    sWd = reinterpret_cast<float*>(smraw + WD_OFF);      // [256*16]
    float*    sbd = reinterpret_cast<float*>(smraw + BD_OFF);      // [16]

    const int cta  = blockIdx.x;
    const int tid  = threadIdx.x;
    const int w    = tid >> 5;
    const int lane = tid & 31;
    const int g    = lane >> 2;
    const int t    = lane & 3;
    const int wm   = w >> 3;              // m-half: rows [32wm, 32wm+32)
    const int wn   = w & 7;               // n-slice of 32

    // ---- stage Wd/bd ----
    #pragma unroll
    for (int i = tid; i < HID * 16; i += 512) sWd[i] = Wd[i];
    if (tid < 16) sbd[tid] = bd[tid];

    // ---- gather: h0 -> split pairs ----
    {
        int r  = tid >> 3;            // row 0..63
        int qt = tid & 7;             // column eighth
        int aid = ids[cta * MAG + r];
        const float4* er = reinterpret_cast<const float4*>(emb + aid * HID);
        #pragma unroll
        for (int q = 0; q < 8; ++q) {
            int f = qt * 8 + q;       // float4 index 0..63
            float4 e = er[f];
            int pair = 2 * f;
            uint2 pa = split2(e.x, e.y);
            uint2 pb = split2(e.z, e.w);
            sHi[pair * PITCH + r]       = pa.x; sLo[pair * PITCH + r]       = pa.y;
            sHi[(pair + 1) * PITCH + r] = pb.x; sLo[(pair + 1) * PITCH + r] = pb.y;
        }
    }

    float* gp = gG0 + (size_t)cta * 16384 + tid;

    for (int step = 0; step < STEPS; ++step) {
        __syncthreads();

        // ---- Sv[k] = sum_m h[m][k]: warp handles 8 pairs, lanes scan m ----
        #pragma unroll
        for (int pi = 0; pi < 8; ++pi) {
            int p = w * 8 + pi;
            float2 v0 = unsplit(sHi[p * PITCH + lane],      sLo[p * PITCH + lane]);
            float2 v1 = unsplit(sHi[p * PITCH + lane + 32], sLo[p * PITCH + lane + 32]);
            float se = v0.x + v1.x, so = v0.y + v1.y;
            #pragma unroll
            for (int off = 16; off; off >>= 1) {
                se += __shfl_xor_sync(0xFFFFFFFFu, se, off);
                so += __shfl_xor_sync(0xFFFFFFFFu, so, off);
            }
            if (lane == 0) { Sv[2 * p] = se; Sv[2 * p + 1] = so; }
        }
        __syncthreads();

        // ---- Tv[c] = b1[c] + inv * (Sv @ W1b)[c] ----
        #pragma unroll 2
        for (int i = 0; i < 16; ++i) {
            int c = w * 16 + i;
            float p0 = 0.f;
            #pragma unroll
            for (int q = 0; q < 8; ++q) {
                int k = lane + 32 * q;
                p0 = fmaf(Sv[k], __ldg(&gW1bT[c * HID + k]), p0);
            }
            #pragma unroll
            for (int off = 16; off; off >>= 1)
                p0 += __shfl_xor_sync(0xFFFFFFFFu, p0, off);
            if (lane == 0) Tv[c] = fmaf(p0, INVF, __ldg(&b1[c]));
        }

        // ---- GEMM1 ----
        float acc[2][4][4];
        if (step == 0) {
            #pragma unroll
            for (int mt = 0; mt < 2; ++mt)
                #pragma unroll
                for (int jn = 0; jn < 4; ++jn)
                    #pragma unroll
                    for (int q = 0; q < 4; ++q) acc[mt][jn][q] = 0.f;
            gemm_pass(gPk2[1], acc, sHi, wm, wn, lane, g, t);       // G0 = h0@W1c
            #pragma unroll
            for (int mt = 0; mt < 2; ++mt)
                #pragma unroll
                for (int jn = 0; jn < 4; ++jn)
                    #pragma unroll
                    for (int q = 0; q < 4; ++q)
                        gp[(((mt * 4 + jn) * 4) + q) * 512] = acc[mt][jn][q];
        } else {
            #pragma unroll
            for (int mt = 0; mt < 2; ++mt)
                #pragma unroll
                for (int jn = 0; jn < 4; ++jn)
                    #pragma unroll
                    for (int q = 0; q < 4; ++q)
                        acc[mt][jn][q] = gp[(((mt * 4 + jn) * 4) + q) * 512];
        }
        gemm_pass(gPk2[0], acc, sHi, wm, wn, lane, g, t);           // += h@W1eff
        __syncthreads();

        // ---- epilogue1: act = relu(acc+Tv) -> s* ; acc = h_old + b2 ----
        #pragma unroll
        for (int mt = 0; mt < 2; ++mt) {
            const int m0 = wm * 32 + mt * 16 + g;
            #pragma unroll
            for (int jn = 0; jn < 4; ++jn) {
                const int pair = 16 * wn + 4 * jn + t;
                const int n0   = 32 * wn + 8 * jn + 2 * t;
                const int i0 = pair * PITCH + m0;
                float2 hoa = unsplit(sHi[i0],     sLo[i0]);
                float2 hob = unsplit(sHi[i0 + 8], sLo[i0 + 8]);
                float tv0 = Tv[n0], tv1 = Tv[n0 + 1];
                float a0 = fmaxf(acc[mt][jn][0] + tv0, 0.f);
                float a1 = fmaxf(acc[mt][jn][1] + tv1, 0.f);
                float a2 = fmaxf(acc[mt][jn][2] + tv0, 0.f);
                float a3 = fmaxf(acc[mt][jn][3] + tv1, 0.f);
                uint2 pa = split2(a0, a1);
                uint2 pb = split2(a2, a3);
                sHi[i0] = pa.x;     sLo[i0] = pa.y;
                sHi[i0 + 8] = pb.x; sLo[i0 + 8] = pb.y;
                float bb0 = __ldg(&b2[n0]), bb1 = __ldg(&b2[n0 + 1]);
                acc[mt][jn][0] = hoa.x + bb0; acc[mt][jn][1] = hoa.y + bb1;
                acc[mt][jn][2] = hob.x + bb0; acc[mt][jn][3] = hob.y + bb1;
            }
        }
        __syncthreads();

        // ---- GEMM2: acc += act @ W2   (acc = new h) ----
        gemm_pass(gPk2[2], acc, sHi, wm, wn, lane, g, t);
        __syncthreads();

        // ---- epilogue2: split new h -> s* ----
        #pragma unroll
        for (int mt = 0; mt < 2; ++mt) {
            const int m0 = wm * 32 + mt * 16 + g;
            #pragma unroll
            for (int jn = 0; jn < 4; ++jn) {
                const int i0 = (16 * wn + 4 * jn + t) * PITCH + m0;
                uint2 pa = split2(acc[mt][jn][0], acc[mt][jn][1]);
                uint2 pb = split2(acc[mt][jn][2], acc[mt][jn][3]);
                sHi[i0] = pa.x;     sLo[i0] = pa.y;
                sHi[i0 + 8] = pb.x; sLo[i0 + 8] = pb.y;
            }
        }
    }

    __syncthreads();
    // ---- logits: out[row][:] = h[row] @ Wd + bd ----
    {
        int m = tid >> 3;               // local row 0..63
        int a = (tid & 7) * 2;          // 2 actions each
        float s0 = sbd[a], s1 = sbd[a + 1];
        #pragma unroll 4
        for (int pair = 0; pair < 128; ++pair) {
            float2 hp = unsplit(sHi[pair * PITCH + m], sLo[pair * PITCH + m]);
            const float2 w0 = *reinterpret_cast<const float2*>(sWd + (2 * pair) * 16 + a);
            const float2 w1 = *reinterpret_cast<const float2*>(sWd + (2 * pair + 1) * 16 + a);
            s0 = fmaf(hp.x, w0.x, fmaf(hp.y, w1.x, s0));
            s1 = fmaf(hp.x, w0.y, fmaf(hp.y, w1.y, s1));
        }
        *reinterpret_cast<float2*>(out + (cta * MAG + m) * 16 + a) = make_float2(s0, s1);
    }
}

extern "C" void kernel_launch(void* const* d_in, const int* in_sizes, int n_in,
                              void* d_out, int out_size)
{
    const int*   ids = (const int*)  d_in[0];
    const float* emb = (const float*)d_in[1];
    const float* W1  = (const float*)d_in[2];
    const float* b1  = (const float*)d_in[3];
    const float* W2  = (const float*)d_in[4];
    const float* b2  = (const float*)d_in[5];
    const float* Wd  = (const float*)d_in[6];
    const float* bd  = (const float*)d_in[7];
    float* out = (float*)d_out;

    const int nCTA = in_sizes[0] / MAG;       // 1024

    prep_all<<<448, 256>>>(W1, W2);

    cudaFuncSetAttribute(commnet_mma_kernel,
                         cudaFuncAttributeMaxDynamicSharedMemorySize, SMEM_BYTES);
    commnet_mma_kernel<<<nCTA, 512, SMEM_BYTES>>>(ids, b1, b2, Wd, bd, emb, out);
}

// round 12
// speedup vs baseline: 2.8663x; 1.3217x over previous
#include <cuda_runtime.h>
#include <cuda_fp16.h>
#include <cstdint>

// ============================================================================
// CommNet via mma.sync m16n8k16 fp16 (compute_100-safe).
// 1 batch per CTA (M=64), grid=1024, 512 threads = 16 warps tiled 2(m) x 8(n).
// 2 CTAs/SM. h state in SMEM as hi/lo fp16x2 split pairs; MMAs consume hi only.
// Round-12: kernel is L1/LSU-bound (L1=78%, tensor=29%) -> move LSU work to
// the idle tensor pipe:
//   * Tv = b1 + inv*(Sv@W1b) computed by MMA (Sv as 16x256 A-tile, rows 0/1 =
//     fp16 hi/lo of Sv, rows 2-15 zero; B = prescaled inv*W1b fp16 pack).
//   * Sv maintained incrementally from epilogue-2 registers (shfl + smem
//     atomics); full-array Sv read only at step 0.
//   * logits = h @ Wd via MMA on 2 warps (hi+lo, exact-ish).
// G0 = h0 @ W1c computed once (step 0), parked in gmem, re-added steps 1-3.
// ============================================================================

#define HID    256
#define MAG    64
#define STEPS  4
#define INVF   (1.0f/63.0f)
#define PITCH  72              // uint32 pitch of sHi/sLo[pair][*] (conflict-free)
#define SVP    24              // uint32 pitch of sSvA[kpair][row] (t*24%32={0,24,16,8})

// SMEM byte offsets
#define SHI_OFF   0            // 128*72*4 = 36864
#define SLO_OFF   36864
#define SSVA_OFF  73728        // 128*24*4 = 12288 (Sv A-tile, rows 0/1 live)
#define SSVF_OFF  86016        // float[256] raw Sv accumulator
#define STV_OFF   87040        // float[256] Tv
#define SMEM_BYTES 88064

// ---------------- device scratch ----------------
// gPk2[g][(s*32+u)*32+lane] = {b0,b1} fp16x2 B-frags; g: 0=W1eff 1=W1c 2=W2 3=inv*W1b
__device__ uint2 gPk2[4][16384];
__device__ uint2 gWdPk[1024];               // Wd^T fp16 B-frags (N=16: 2 u-tiles)
__device__ float gG0[1024 * 32 * 512];      // [cta][slot32][tid]  (64 MB)

// ---------------- fp16 split helpers ----------------
__device__ __forceinline__ uint2 split2(float x0, float x1) {
    __half2 h = __float22half2_rn(make_float2(x0, x1));    // .x=low=x0
    float2 hf = __half22float2(h);
    __half2 l = __float22half2_rn(make_float2(x0 - hf.x, x1 - hf.y));
    uint2 r;
    r.x = *reinterpret_cast<uint32_t*>(&h);
    r.y = *reinterpret_cast<uint32_t*>(&l);
    return r;
}
__device__ __forceinline__ uint32_t f16x2_single(float x0, float x1) {
    __half2 h = __float22half2_rn(make_float2(x0, x1));
    return *reinterpret_cast<uint32_t*>(&h);
}
__device__ __forceinline__ float2 unsplit(uint32_t hx, uint32_t lx) {
    float2 fh = __half22float2(*reinterpret_cast<__half2*>(&hx));
    float2 fl = __half22float2(*reinterpret_cast<__half2*>(&lx));
    return make_float2(fh.x + fl.x, fh.y + fl.y);
}

#define MMA(c, a, B0, B1)                                                      \
    asm volatile("mma.sync.aligned.m16n8k16.row.col.f32.f16.f16.f32 "          \
                 "{%0,%1,%2,%3},{%4,%5,%6,%7},{%8,%9},{%0,%1,%2,%3};"          \
                 : "+f"((c)[0]), "+f"((c)[1]), "+f"((c)[2]), "+f"((c)[3])      \
                 : "r"((a)[0]), "r"((a)[1]), "r"((a)[2]), "r"((a)[3]),         \
                   "r"(B0), "r"(B1));

// ---------------- prep kernel ----------------
__global__ void prep_all(const float* __restrict__ W1, const float* __restrict__ W2,
                         const float* __restrict__ Wd) {
    int bid = blockIdx.x;
    if (bid < 256) {
        int idx = bid * 256 + threadIdx.x;     // 4 * 16384
        int gm = idx >> 14;
        int r  = idx & 16383;
        int s  = r >> 10;
        int u  = (r >> 5) & 31;
        int l  = r & 31;
        int g  = l >> 2, t = l & 3;
        int n  = u * 8 + g;
        int kb = s * 16 + 2 * t;
        int ks[4] = { kb, kb + 1, kb + 8, kb + 9 };
        float v[4];
        #pragma unroll
        for (int q = 0; q < 4; ++q) {
            int k = ks[q];
            if (gm == 0)      v[q] = W1[k * HID + n] - INVF * W1[(HID + k) * HID + n];
            else if (gm == 1) v[q] = W1[(2 * HID + k) * HID + n];
            else if (gm == 2) v[q] = W2[k * HID + n];
            else              v[q] = INVF * W1[(HID + k) * HID + n];
        }
        gPk2[gm][r] = make_uint2(f16x2_single(v[0], v[1]), f16x2_single(v[2], v[3]));
    } else if (bid == 256) {
        int idx = threadIdx.x;                 // 256 of 1024 per... grid-stride 4x
        for (int e = idx; e < 1024; e += 256) {
            int l = e & 31;
            int u = (e >> 5) & 1;
            int s = e >> 6;
            int g = l >> 2, t = l & 3;
            int n = u * 8 + g;
            int kb = s * 16 + 2 * t;
            int ks[4] = { kb, kb + 1, kb + 8, kb + 9 };
            float v[4];
            #pragma unroll
            for (int q = 0; q < 4; ++q) v[q] = Wd[ks[q] * 16 + n];
            gWdPk[e] = make_uint2(f16x2_single(v[0], v[1]), f16x2_single(v[2], v[3]));
        }
    }
}

// ---------------- GEMM pass: acc += Ahi @ B --------------------------------
__device__ __forceinline__ void gemm_pass(const uint2* __restrict__ bp,
                                          float (&acc)[2][4][4],
                                          const uint32_t* __restrict__ sHi,
                                          int wm, int wn, int lane, int g, int t) {
    const uint2* bq = bp + wn * 128 + lane;
    const int mbase = wm * 32 + g;
    #pragma unroll 2
    for (int s = 0; s < 16; ++s) {
        uint2 cur[4];
        #pragma unroll
        for (int jn = 0; jn < 4; ++jn) cur[jn] = __ldg(bq + s * 1024 + jn * 32);
        const int kp0 = (s * 8 + t) * PITCH + mbase;
        const int kp2 = kp0 + 4 * PITCH;
        #pragma unroll
        for (int mt = 0; mt < 2; ++mt) {
            const int m0 = mt * 16;
            uint32_t ah[4];
            ah[0] = sHi[kp0 + m0]; ah[1] = sHi[kp0 + m0 + 8];
            ah[2] = sHi[kp2 + m0]; ah[3] = sHi[kp2 + m0 + 8];
            #pragma unroll
            for (int jn = 0; jn < 4; ++jn) {
                MMA(acc[mt][jn], ah, cur[jn].x, cur[jn].y);   // Ahi * B
            }
        }
    }
}

// ---------------- main kernel ----------------
__global__ void __launch_bounds__(512, 2) commnet_mma_kernel(
    const int*   __restrict__ ids,
    const float* __restrict__ b1,
    const float* __restrict__ b2,
    const float* __restrict__ bd,
    const float* __restrict__ emb,
    float*       __restrict__ out)
{
    extern __shared__ uint8_t smraw[];
    uint32_t* sHi  = reinterpret_cast<uint32_t*>(smraw + SHI_OFF);   // [128][72]
    uint32_t* sLo  = reinterpret_cast<uint32_t*>(smraw + SLO_OFF);   // [128][72]
    uint32_t* sSvA = reinterpret_cast<uint32_t*>(smraw + SSVA_OFF);  // [128][24]
    float*    sSvF = reinterpret_cast<float*>(smraw + SSVF_OFF);     // [256]
    float*    sTv  = reinterpret_cast<float*>(smraw + STV_OFF);      // [256]

    const int cta  = blockIdx.x;
    const int tid  = threadIdx.x;
    const int w    = tid >> 5;
    const int lane = tid & 31;
    const int g    = lane >> 2;
    const int t    = lane & 3;
    const int wm   = w >> 3;              // m-half: rows [32wm, 32wm+32)
    const int wn   = w & 7;               // n-slice of 32

    // ---- zero Sv A-tile (rows 2-15 stay zero forever) ----
    for (int i = tid; i < 128 * SVP; i += 512) sSvA[i] = 0u;

    // ---- gather: h0 -> split pairs ----
    {
        int r  = tid >> 3;            // row 0..63
        int qt = tid & 7;             // column eighth
        int aid = ids[cta * MAG + r];
        const float4* er = reinterpret_cast<const float4*>(emb + aid * HID);
        #pragma unroll
        for (int q = 0; q < 8; ++q) {
            int f = qt * 8 + q;       // float4 index 0..63
            float4 e = er[f];
            int pair = 2 * f;
            uint2 pa = split2(e.x, e.y);
            uint2 pb = split2(e.z, e.w);
            sHi[pair * PITCH + r]       = pa.x; sLo[pair * PITCH + r]       = pa.y;
            sHi[(pair + 1) * PITCH + r] = pb.x; sLo[(pair + 1) * PITCH + r] = pb.y;
        }
    }

    float* gp = gG0 + (size_t)cta * 16384 + tid;

    for (int step = 0; step < STEPS; ++step) {
        __syncthreads();

        if (step == 0) {
            // ---- initial Sv from smem (full read, step 0 only) ----
            #pragma unroll
            for (int pi = 0; pi < 8; ++pi) {
                int p = w * 8 + pi;
                float2 v0 = unsplit(sHi[p * PITCH + lane],      sLo[p * PITCH + lane]);
                float2 v1 = unsplit(sHi[p * PITCH + lane + 32], sLo[p * PITCH + lane + 32]);
                float se = v0.x + v1.x, so = v0.y + v1.y;
                #pragma unroll
                for (int off = 16; off; off >>= 1) {
                    se += __shfl_xor_sync(0xFFFFFFFFu, se, off);
                    so += __shfl_xor_sync(0xFFFFFFFFu, so, off);
                }
                if (lane == 0) { sSvF[2 * p] = se; sSvF[2 * p + 1] = so; }
            }
            __syncthreads();
        }

        // ---- build Sv A-tile rows 0 (hi) / 1 (lo) ----
        if (tid < 128) {
            float2 sv = *reinterpret_cast<const float2*>(sSvF + 2 * tid);
            uint2 pa = split2(sv.x, sv.y);
            sSvA[tid * SVP + 0] = pa.x;    // row 0: hi
            sSvA[tid * SVP + 1] = pa.y;    // row 1: lo
        }
        __syncthreads();

        // ---- Tv via MMA: Tv = b1 + (Sv_hi + Sv_lo) @ (inv*W1b) ----
        {
            float accT[2][4];
            #pragma unroll
            for (int jl = 0; jl < 2; ++jl)
                #pragma unroll
                for (int q = 0; q < 4; ++q) accT[jl][q] = 0.f;
            const int u0 = wn * 4 + wm * 2;
            const uint2* bq = gPk2[3] + u0 * 32 + lane;
            #pragma unroll 4
            for (int s = 0; s < 16; ++s) {
                uint2 c0 = __ldg(bq + s * 1024);
                uint2 c1 = __ldg(bq + s * 1024 + 32);
                const int kp0 = (s * 8 + t) * SVP;
                uint32_t ah[4];
                ah[0] = sSvA[kp0 + g];           ah[1] = sSvA[kp0 + g + 8];
                ah[2] = sSvA[kp0 + 4 * SVP + g]; ah[3] = sSvA[kp0 + 4 * SVP + g + 8];
                MMA(accT[0], ah, c0.x, c0.y);
                MMA(accT[1], ah, c1.x, c1.y);
            }
            #pragma unroll
            for (int jl = 0; jl < 2; ++jl) {
                int n0 = (u0 + jl) * 8 + 2 * t;
                float d0 = accT[jl][0], d1 = accT[jl][1];
                float r0 = __shfl_down_sync(0xFFFFFFFFu, d0, 4);   // row 1 (lo)
                float r1 = __shfl_down_sync(0xFFFFFFFFu, d1, 4);
                if (g == 0) {
                    float2 bb = *reinterpret_cast<const float2*>(b1 + n0);
                    reinterpret_cast<float2*>(sTv)[n0 >> 1] =
                        make_float2(d0 + r0 + bb.x, d1 + r1 + bb.y);
                }
            }
        }

        // ---- GEMM1 ----
        float acc[2][4][4];
        if (step == 0) {
            #pragma unroll
            for (int mt = 0; mt < 2; ++mt)
                #pragma unroll
                for (int jn = 0; jn < 4; ++jn)
                    #pragma unroll
                    for (int q = 0; q < 4; ++q) acc[mt][jn][q] = 0.f;
            gemm_pass(gPk2[1], acc, sHi, wm, wn, lane, g, t);       // G0 = h0@W1c
            #pragma unroll
            for (int mt = 0; mt < 2; ++mt)
                #pragma unroll
                for (int jn = 0; jn < 4; ++jn)
                    #pragma unroll
                    for (int q = 0; q < 4; ++q)
                        gp[(((mt * 4 + jn) * 4) + q) * 512] = acc[mt][jn][q];
        } else {
            #pragma unroll
            for (int mt = 0; mt < 2; ++mt)
                #pragma unroll
                for (int jn = 0; jn < 4; ++jn)
                    #pragma unroll
                    for (int q = 0; q < 4; ++q)
                        acc[mt][jn][q] = gp[(((mt * 4 + jn) * 4) + q) * 512];
        }
        gemm_pass(gPk2[0], acc, sHi, wm, wn, lane, g, t);           // += h@W1eff
        __syncthreads();

        // ---- epilogue1: act = relu(acc+Tv) -> s* ; acc = h_old + b2 ----
        if (tid < 128)     // zero raw-Sv accumulator for the NEXT step
            reinterpret_cast<float2*>(sSvF)[tid] = make_float2(0.f, 0.f);
        #pragma unroll
        for (int mt = 0; mt < 2; ++mt) {
            const int m0 = wm * 32 + mt * 16 + g;
            #pragma unroll
            for (int jn = 0; jn < 4; ++jn) {
                const int pair = 16 * wn + 4 * jn + t;
                const int n0   = 32 * wn + 8 * jn + 2 * t;
                const int i0 = pair * PITCH + m0;
                float2 hoa = unsplit(sHi[i0],     sLo[i0]);
                float2 hob = unsplit(sHi[i0 + 8], sLo[i0 + 8]);
                float tv0 = sTv[n0], tv1 = sTv[n0 + 1];
                float a0 = fmaxf(acc[mt][jn][0] + tv0, 0.f);
                float a1 = fmaxf(acc[mt][jn][1] + tv1, 0.f);
                float a2 = fmaxf(acc[mt][jn][2] + tv0, 0.f);
                float a3 = fmaxf(acc[mt][jn][3] + tv1, 0.f);
                uint2 pa = split2(a0, a1);
                uint2 pb = split2(a2, a3);
                sHi[i0] = pa.x;     sLo[i0] = pa.y;
                sHi[i0 + 8] = pb.x; sLo[i0 + 8] = pb.y;
                float bb0 = __ldg(&b2[n0]), bb1 = __ldg(&b2[n0 + 1]);
                acc[mt][jn][0] = hoa.x + bb0; acc[mt][jn][1] = hoa.y + bb1;
                acc[mt][jn][2] = hob.x + bb0; acc[mt][jn][3] = hob.y + bb1;
            }
        }
        __syncthreads();

        // ---- GEMM2: acc += act @ W2   (acc = new h) ----
        gemm_pass(gPk2[2], acc, sHi, wm, wn, lane, g, t);
        __syncthreads();

        // ---- epilogue2: split new h -> s*; accumulate next Sv ----
        #pragma unroll
        for (int mt = 0; mt < 2; ++mt) {
            const int m0 = wm * 32 + mt * 16 + g;
            #pragma unroll
            for (int jn = 0; jn < 4; ++jn) {
                const int i0 = (16 * wn + 4 * jn + t) * PITCH + m0;
                uint2 pa = split2(acc[mt][jn][0], acc[mt][jn][1]);
                uint2 pb = split2(acc[mt][jn][2], acc[mt][jn][3]);
                sHi[i0] = pa.x;     sLo[i0] = pa.y;
                sHi[i0 + 8] = pb.x; sLo[i0 + 8] = pb.y;
            }
        }
        #pragma unroll
        for (int jn = 0; jn < 4; ++jn) {
            float s0 = acc[0][jn][0] + acc[0][jn][2] + acc[1][jn][0] + acc[1][jn][2];
            float s1 = acc[0][jn][1] + acc[0][jn][3] + acc[1][jn][1] + acc[1][jn][3];
            #pragma unroll
            for (int off = 4; off <= 16; off <<= 1) {      // sum over g (lane bits 2-4)
                s0 += __shfl_xor_sync(0xFFFFFFFFu, s0, off);
                s1 += __shfl_xor_sync(0xFFFFFFFFu, s1, off);
            }
            if (g == 0) {
                int n0 = 32 * wn + 8 * jn + 2 * t;
                atomicAdd(&sSvF[n0],     s0);
                atomicAdd(&sSvF[n0 + 1], s1);
            }
        }
    }

    __syncthreads();
    // ---- logits via MMA on warps wn==0: out = h @ Wd + bd  (hi+lo terms) ----
    if (wn == 0) {
        float accL[2][2][4];
        #pragma unroll
        for (int mt = 0; mt < 2; ++mt)
            #pragma unroll
            for (int jl = 0; jl < 2; ++jl) {
                int n0 = 8 * jl + 2 * t;
                float2 bv = *reinterpret_cast<const float2*>(bd + n0);
                accL[mt][jl][0] = bv.x; accL[mt][jl][1] = bv.y;
                accL[mt][jl][2] = bv.x; accL[mt][jl][3] = bv.y;
            }
        const int mbase = wm * 32 + g;
        #pragma unroll 4
        for (int s = 0; s < 16; ++s) {
            uint2 c0 = __ldg(&gWdPk[(s * 2 + 0) * 32 + lane]);
            uint2 c1 = __ldg(&gWdPk[(s * 2 + 1) * 32 + lane]);
            const int kp0 = (s * 8 + t) * PITCH + mbase;
            const int kp2 = kp0 + 4 * PITCH;
            #pragma unroll
            for (int mt = 0; mt < 2; ++mt) {
                const int m0 = mt * 16;
                uint32_t ah[4], al[4];
                ah[0] = sHi[kp0 + m0]; ah[1] = sHi[kp0 + m0 + 8];
                ah[2] = sHi[kp2 + m0]; ah[3] = sHi[kp2 + m0 + 8];
                al[0] = sLo[kp0 + m0]; al[1] = sLo[kp0 + m0 + 8];
                al[2] = sLo[kp2 + m0]; al[3] = sLo[kp2 + m0 + 8];
                MMA(accL[mt][0], ah, c0.x, c0.y);
                MMA(accL[mt][0], al, c0.x, c0.y);
                MMA(accL[mt][1], ah, c1.x, c1.y);
                MMA(accL[mt][1], al, c1.x, c1.y);
            }
        }
        #pragma unroll
        for (int mt = 0; mt < 2; ++mt) {
            const int m0 = wm * 32 + mt * 16 + g;
            #pragma unroll
            for (int jl = 0; jl < 2; ++jl) {
                const int n0 = 8 * jl + 2 * t;
                *reinterpret_cast<float2*>(out + (cta * MAG + m0) * 16 + n0) =
                    make_float2(accL[mt][jl][0], accL[mt][jl][1]);
                *reinterpret_cast<float2*>(out + (cta * MAG + m0 + 8) * 16 + n0) =
                    make_float2(accL[mt][jl][2], accL[mt][jl][3]);
            }
        }
    }
}

extern "C" void kernel_launch(void* const* d_in, const int* in_sizes, int n_in,
                              void* d_out, int out_size)
{
    const int*   ids = (const int*)  d_in[0];
    const float* emb = (const float*)d_in[1];
    const float* W1  = (const float*)d_in[2];
    const float* b1  = (const float*)d_in[3];
    const float* W2  = (const float*)d_in[4];
    const float* b2  = (const float*)d_in[5];
    const float* Wd  = (const float*)d_in[6];
    const float* bd  = (const float*)d_in[7];
    float* out = (float*)d_out;

    const int nCTA = in_sizes[0] / MAG;       // 1024

    prep_all<<<257, 256>>>(W1, W2, Wd);

    cudaFuncSetAttribute(commnet_mma_kernel,
                         cudaFuncAttributeMaxDynamicSharedMemorySize, SMEM_BYTES);
    commnet_mma_kernel<<<nCTA, 512, SMEM_BYTES>>>(ids, b1, b2, bd, emb, out);
}